// round 11
// baseline (speedup 1.0000x reference)
#include <cuda_runtime.h>
#include <cuda_bf16.h>
#include <cuda_pipeline.h>
#include <mma.h>
#include <math.h>

using namespace nvcuda;

#define NN    50000
#define EE    800000
#define ETOT  (EE + NN)
#define FIN   78
#define H1C   10
#define D1    (H1C * FIN)   // 780
#define OUT2C 128
#define GC    512
#define SLOPE 0.2f
#define CHUNK 64
#define PROJ_BLOCKS ((NN + 31) / 32)       // 1563
#define EDGE_BLOCKS ((ETOT + 255) / 256)   // 3321

// ---------------- scratch ----------------
__device__ float g_agg[(size_t)NN * D1];
__device__ float g_o1 [(size_t)NN * D1];
__device__ float g_h2 [(size_t)NN * OUT2C];
__device__ float g_o2 [(size_t)NN * OUT2C];
__device__ float g_as1[(size_t)NN * H1C];
__device__ float g_ad1[(size_t)NN * H1C];
__device__ float g_as2[NN];
__device__ float g_ad2[NN];
__device__ float g_p  [20 * FIN];
__device__ int   g_deg[NN + 1];            // zero-init; re-zeroed by cleanup
__device__ int   g_rowptr[NN + 1];
__device__ int   g_cursor[NN];
__device__ int   g_csrsrc[ETOT];
__device__ int   g_gstart[GC + 1];

// ---------------- helpers ----------------
__device__ __forceinline__ void atomicMaxF(float* addr, float val) {
    if (!signbit(val)) atomicMax((int*)addr, __float_as_int(val));
    else               atomicMin((unsigned int*)addr, __float_as_uint(val));
}
__device__ __forceinline__ void edge_nodes(const int* __restrict__ ei, int t, int& s, int& d) {
    if (t < EE) { s = ei[t]; d = ei[EE + t]; }
    else        { s = t - EE; d = t - EE; }
}

// ---------------- 1: histogram ----------------
__global__ void hist_kernel(const int* __restrict__ ei, int* __restrict__ deg) {
    int t = blockIdx.x * blockDim.x + threadIdx.x;
    if (t >= ETOT) return;
    int s, d; edge_nodes(ei, t, s, d);
    atomicAdd(&deg[d], 1);
}

// ---------------- 2: scan (shuffle-based) + attention-vector projection -----
__global__ void scan50k(const int* __restrict__ deg, int* __restrict__ rowptr,
                        int* __restrict__ cur,
                        const float* __restrict__ W1, const float* __restrict__ a_src,
                        const float* __restrict__ a_dst, float* __restrict__ p)
{
    for (int idx = threadIdx.x; idx < 20 * FIN; idx += 1024) {
        int o = idx / FIN, k = idx - o * FIN;
        int h = (o < H1C) ? o : o - H1C;
        const float* av = (o < H1C) ? (a_src + h * FIN) : (a_dst + h * FIN);
        const float* wrow = W1 + (size_t)k * D1 + h * FIN;
        float s = 0.f;
        #pragma unroll 13
        for (int f = 0; f < FIN; f++) s += wrow[f] * av[f];
        p[idx] = s;
    }

    __shared__ int warpsum[32];
    __shared__ int carry_s;
    int tid = threadIdx.x, lane = tid & 31, warp = tid >> 5;
    if (tid == 0) carry_s = 0;
    __syncthreads();

    for (int base = 0; base < NN; base += 1024) {
        int i = base + tid;
        int v = (i < NN) ? deg[i] : 0;
        int s = v;
        #pragma unroll
        for (int o = 1; o < 32; o <<= 1) {
            int t = __shfl_up_sync(0xffffffffu, s, o);
            if (lane >= o) s += t;
        }
        if (lane == 31) warpsum[warp] = s;
        __syncthreads();
        if (warp == 0) {
            int ws = warpsum[lane];
            int e = ws;
            #pragma unroll
            for (int o = 1; o < 32; o <<= 1) {
                int t = __shfl_up_sync(0xffffffffu, e, o);
                if (lane >= o) e += t;
            }
            warpsum[lane] = e - ws;   // exclusive warp offset
        }
        __syncthreads();
        int excl = carry_s + warpsum[warp] + s - v;
        if (i < NN) { rowptr[i] = excl; cur[i] = excl; }
        __syncthreads();
        if (tid == 1023) carry_s = excl + v;
        __syncthreads();
    }
    if (threadIdx.x == 0) rowptr[NN] = carry_s;
}

// ---------------- 3: CSR scatter + per-node logits as1/ad1 ------------------
__global__ __launch_bounds__(256) void csr_scatter_proj(
    const int* __restrict__ ei, int* __restrict__ cur, int* __restrict__ csrsrc,
    const float* __restrict__ x, const float* __restrict__ p,
    float* __restrict__ as, float* __restrict__ ad)
{
    int b = blockIdx.x, tid = threadIdx.x;
    int t = b * 256 + tid;
    if (t < ETOT) {
        int s, d; edge_nodes(ei, t, s, d);
        int pos = atomicAdd(&cur[d], 1);
        csrsrc[pos] = s;
    }

    if (b < PROJ_BLOCKS) {
        __shared__ float xs[32][80];
        __shared__ float ps[20][80];
        int nodeBase = b * 32;
        for (int idx = tid; idx < 20 * FIN; idx += 256) {
            int o = idx / FIN, k = idx - o * FIN;
            ps[o][k] = p[idx];
        }
        for (int idx = tid; idx < 32 * FIN; idx += 256) {
            int i = idx / FIN, k = idx - i * FIN;
            int n = nodeBase + i;
            xs[i][k] = (n < NN) ? x[(size_t)n * FIN + k] : 0.f;
        }
        __syncthreads();
        for (int s = tid; s < 32 * 20; s += 256) {
            int i = s / 20, o = s - i * 20;
            int n = nodeBase + i;
            if (n >= NN) continue;
            float acc = 0.f;
            #pragma unroll 13
            for (int k = 0; k < FIN; k++) acc += xs[i][k] * ps[o][k];
            if (o < H1C) as[n * H1C + o] = acc;
            else         ad[n * H1C + (o - H1C)] = acc;
        }
    }
}

// ---------------- 4: layer-1 gather (warp staging + vector logits) ----------
__global__ __launch_bounds__(256) void gather1x(
    const int* __restrict__ rowptr, const int* __restrict__ csrsrc,
    const float* __restrict__ as, const float* __restrict__ ad,
    const float* __restrict__ x, float* __restrict__ agg)
{
    int d = blockIdx.x;
    int tid = threadIdx.x;
    int lane = tid & 31, warp = tid >> 5;
    int beg = rowptr[d], end = rowptr[d + 1];
    int deg = end - beg;

    __shared__ float m[H1C];
    __shared__ float den[H1C];
    __shared__ float adv[H1C];
    __shared__ int   s_src[CHUNK];
    __shared__ float w[CHUNK][H1C];
    __shared__ __align__(16) float xs[CHUNK][80];

    if (tid < H1C) {
        adv[tid] = ad[d * H1C + tid];
        m[tid] = -INFINITY;
        den[tid] = 0.f;
    }
    __syncthreads();

    const bool active = tid < 200;
    int hh = tid / 20;
    int f4 = (tid % 20) * 4;
    float a0 = 0.f, a1 = 0.f, a2 = 0.f, a3 = 0.f;

    if (deg <= CHUNK) {
        if (tid < deg) s_src[tid] = csrsrc[beg + tid];
        __syncthreads();
        // warp-per-edge float2 staging (x rows are 8B-aligned: 312B stride)
        for (int e = warp; e < deg; e += 8) {
            const float2* xr = reinterpret_cast<const float2*>(x + (size_t)s_src[e] * FIN);
            float2* xd = reinterpret_cast<float2*>(xs[e]);
            for (int k = lane; k < 39; k += 32) xd[k] = xr[k];
            if (lane == 0) { xs[e][78] = 0.f; xs[e][79] = 0.f; }
        }
        // thread-per-edge logits: 10 contiguous alphas via float2
        if (tid < deg) {
            const float2* ap = reinterpret_cast<const float2*>(as + (size_t)s_src[tid] * H1C);
            float2 t0 = ap[0], t1 = ap[1], t2 = ap[2], t3 = ap[3], t4 = ap[4];
            float lg[10] = {t0.x, t0.y, t1.x, t1.y, t2.x, t2.y, t3.x, t3.y, t4.x, t4.y};
            #pragma unroll
            for (int h = 0; h < H1C; h++) {
                float v = lg[h] + adv[h];
                v = v > 0.f ? v : SLOPE * v;
                w[tid][h] = v;
                atomicMaxF(&m[h], v);
            }
        }
        __syncthreads();
        if (tid < deg) {
            #pragma unroll
            for (int h = 0; h < H1C; h++) {
                float ww = __expf(w[tid][h] - m[h]);
                w[tid][h] = ww;
                atomicAdd(&den[h], ww);
            }
        }
        __syncthreads();
        if (active) {
            for (int e = 0; e < deg; e++) {
                float4 xv = *(const float4*)&xs[e][f4];
                float ww = w[e][hh];
                a0 += xv.x * ww; a1 += xv.y * ww; a2 += xv.z * ww; a3 += xv.w * ww;
            }
        }
    } else {
        // max pass: thread-per-edge strided, register maxima, 10 atomics/thread
        if (tid < deg) {
            float mloc[10];
            #pragma unroll
            for (int h = 0; h < H1C; h++) mloc[h] = -INFINITY;
            for (int t = tid; t < deg; t += 256) {
                const float2* ap = reinterpret_cast<const float2*>(as + (size_t)csrsrc[beg + t] * H1C);
                float2 t0 = ap[0], t1 = ap[1], t2 = ap[2], t3 = ap[3], t4 = ap[4];
                float lg[10] = {t0.x, t0.y, t1.x, t1.y, t2.x, t2.y, t3.x, t3.y, t4.x, t4.y};
                #pragma unroll
                for (int h = 0; h < H1C; h++) {
                    float v = lg[h] + adv[h];
                    v = v > 0.f ? v : SLOPE * v;
                    mloc[h] = fmaxf(mloc[h], v);
                }
            }
            #pragma unroll
            for (int h = 0; h < H1C; h++) atomicMaxF(&m[h], mloc[h]);
        }
        __syncthreads();
        for (int cbeg = 0; cbeg < deg; cbeg += CHUNK) {
            int clen = min(CHUNK, deg - cbeg);
            if (tid < clen) s_src[tid] = csrsrc[beg + cbeg + tid];
            __syncthreads();
            for (int e = warp; e < clen; e += 8) {
                const float2* xr = reinterpret_cast<const float2*>(x + (size_t)s_src[e] * FIN);
                float2* xd = reinterpret_cast<float2*>(xs[e]);
                for (int k = lane; k < 39; k += 32) xd[k] = xr[k];
                if (lane == 0) { xs[e][78] = 0.f; xs[e][79] = 0.f; }
            }
            if (tid < clen) {
                const float2* ap = reinterpret_cast<const float2*>(as + (size_t)s_src[tid] * H1C);
                float2 t0 = ap[0], t1 = ap[1], t2 = ap[2], t3 = ap[3], t4 = ap[4];
                float lg[10] = {t0.x, t0.y, t1.x, t1.y, t2.x, t2.y, t3.x, t3.y, t4.x, t4.y};
                #pragma unroll
                for (int h = 0; h < H1C; h++) {
                    float v = lg[h] + adv[h];
                    v = v > 0.f ? v : SLOPE * v;
                    float ww = __expf(v - m[h]);
                    w[tid][h] = ww;
                    atomicAdd(&den[h], ww);
                }
            }
            __syncthreads();
            if (active) {
                for (int e = 0; e < clen; e++) {
                    float4 xv = *(const float4*)&xs[e][f4];
                    float ww = w[e][hh];
                    a0 += xv.x * ww; a1 += xv.y * ww; a2 += xv.z * ww; a3 += xv.w * ww;
                }
            }
            __syncthreads();
        }
    }
    __syncthreads();

    if (active) {
        float inv = 1.f / (den[hh] + 1e-16f);
        float* op = agg + (size_t)d * D1 + hh * FIN + f4;
        op[0] = a0 * inv;
        if (f4 + 1 < FIN) op[1] = a1 * inv;
        if (f4 + 2 < FIN) op[2] = a2 * inv;
        if (f4 + 3 < FIN) op[3] = a3 * inv;
    }
}

// ---------------- 5: block-diagonal GEMM + bias + relu ----------------------
#define BK1 26
__global__ __launch_bounds__(256) void gemm_head(
    const float* __restrict__ agg, const float* __restrict__ W1,
    const float* __restrict__ b1, float* __restrict__ out1)
{
    __shared__ float As[BK1][128];
    __shared__ float Bs[BK1][80];
    int h = blockIdx.y;
    int rowBase = blockIdx.x * 128;
    int tid = threadIdx.x;
    int ty = tid >> 3;
    int tx = tid & 7;
    int r0 = ty * 4;

    float acc[4][10] = {};

    for (int k0 = 0; k0 < FIN; k0 += BK1) {
        for (int idx = tid; idx < 128 * BK1; idx += 256) {
            int r = idx / BK1, c = idx - r * BK1;
            int gr = rowBase + r;
            As[c][r] = (gr < NN) ? agg[(size_t)gr * D1 + h * FIN + k0 + c] : 0.f;
        }
        for (int idx = tid; idx < BK1 * FIN; idx += 256) {
            int r = idx / FIN, c = idx - r * FIN;
            Bs[r][c] = W1[(size_t)(k0 + r) * D1 + h * FIN + c];
        }
        __syncthreads();
        #pragma unroll
        for (int k = 0; k < BK1; k++) {
            float a0 = As[k][r0], a1 = As[k][r0 + 1], a2 = As[k][r0 + 2], a3 = As[k][r0 + 3];
            float b[10];
            #pragma unroll
            for (int j = 0; j < 10; j++) b[j] = Bs[k][tx * 10 + j];
            #pragma unroll
            for (int j = 0; j < 10; j++) {
                acc[0][j] += a0 * b[j];
                acc[1][j] += a1 * b[j];
                acc[2][j] += a2 * b[j];
                acc[3][j] += a3 * b[j];
            }
        }
        __syncthreads();
    }

    #pragma unroll
    for (int i = 0; i < 4; i++) {
        int gr = rowBase + r0 + i;
        if (gr >= NN) continue;
        #pragma unroll
        for (int j = 0; j < 10; j++) {
            int gc = tx * 10 + j;
            if (gc < FIN) {
                float v = acc[i][j] + b1[h * FIN + gc];
                out1[(size_t)gr * D1 + h * FIN + gc] = v > 0.f ? v : 0.f;
            }
        }
    }
}

// ---------------- 6: layer-2 GEMM, TF32 tensor cores, cp.async pipeline -----
#define K2    780
#define NCH   49
#define LDAS  20
#define LDBS  136

__global__ __launch_bounds__(256) void gemm2_tf32(
    const float* __restrict__ A, const float* __restrict__ B, float* __restrict__ C, int M)
{
    __shared__ float As[2][128][LDAS];
    __shared__ float Bs[2][16][LDBS];

    int tid = threadIdx.x;
    int warp = tid >> 5;
    int warp_m = warp & 3;
    int warp_n = warp >> 2;
    int rowBase = blockIdx.x * 128;

    wmma::fragment<wmma::accumulator, 16, 16, 8, float> acc[2][4];
    #pragma unroll
    for (int i = 0; i < 2; i++)
        #pragma unroll
        for (int j = 0; j < 4; j++) wmma::fill_fragment(acc[i][j], 0.f);

    auto load_stage = [&](int ch, int buf) {
        int k0 = ch * 16;
        #pragma unroll
        for (int l = 0; l < 2; l++) {
            int idx = tid + l * 256;
            int r = idx >> 2, c4 = idx & 3;
            int gr = rowBase + r;
            int gk = k0 + c4 * 4;
            bool valid = (gr < M) && (gk < K2);
            const float* src = A + (size_t)gr * K2 + gk;
            __pipeline_memcpy_async(&As[buf][r][c4 * 4], src, 16, valid ? 0 : 16);
        }
        #pragma unroll
        for (int l = 0; l < 2; l++) {
            int idx = tid + l * 256;
            int r = idx >> 5, c = idx & 31;
            int gk = k0 + r;
            bool valid = (gk < K2);
            const float* src = B + (size_t)gk * OUT2C + c * 4;
            __pipeline_memcpy_async(&Bs[buf][r][c * 4], src, 16, valid ? 0 : 16);
        }
        __pipeline_commit();
    };

    load_stage(0, 0);

    for (int ch = 0; ch < NCH; ch++) {
        int buf = ch & 1;
        if (ch + 1 < NCH) load_stage(ch + 1, (ch + 1) & 1);
        __pipeline_wait_prior((ch + 1 < NCH) ? 1 : 0);
        __syncthreads();

        #pragma unroll
        for (int kk = 0; kk < 16; kk += 8) {
            wmma::fragment<wmma::matrix_a, 16, 16, 8, wmma::precision::tf32, wmma::row_major> af[2];
            wmma::fragment<wmma::matrix_b, 16, 16, 8, wmma::precision::tf32, wmma::row_major> bf[4];
            #pragma unroll
            for (int i = 0; i < 2; i++) {
                wmma::load_matrix_sync(af[i], &As[buf][warp_m * 32 + i * 16][kk], LDAS);
                #pragma unroll
                for (int t = 0; t < af[i].num_elements; t++)
                    af[i].x[t] = wmma::__float_to_tf32(af[i].x[t]);
            }
            #pragma unroll
            for (int j = 0; j < 4; j++) {
                wmma::load_matrix_sync(bf[j], &Bs[buf][kk][warp_n * 64 + j * 16], LDBS);
                #pragma unroll
                for (int t = 0; t < bf[j].num_elements; t++)
                    bf[j].x[t] = wmma::__float_to_tf32(bf[j].x[t]);
            }
            #pragma unroll
            for (int i = 0; i < 2; i++)
                #pragma unroll
                for (int j = 0; j < 4; j++)
                    wmma::mma_sync(acc[i][j], af[i], bf[j], acc[i][j]);
        }
        __syncthreads();
    }

    #pragma unroll
    for (int i = 0; i < 2; i++) {
        int gr = rowBase + warp_m * 32 + i * 16;
        if (gr >= M) continue;
        #pragma unroll
        for (int j = 0; j < 4; j++) {
            int gc = warp_n * 64 + j * 16;
            wmma::store_matrix_sync(&C[(size_t)gr * OUT2C + gc], acc[i][j], OUT2C, wmma::mem_row_major);
        }
    }
}

// ---------------- 7: layer-2 attention projections --------------------------
__global__ void alpha_proj(const float* __restrict__ h,
                           const float* __restrict__ a_src, const float* __restrict__ a_dst,
                           float* __restrict__ as, float* __restrict__ ad,
                           int n, int heads, int dim)
{
    int gw = (blockIdx.x * blockDim.x + threadIdx.x) >> 5;
    int lane = threadIdx.x & 31;
    if (gw >= n * heads) return;
    int node = gw / heads, hd = gw - node * heads;
    const float* hp = h + (size_t)node * heads * dim + (size_t)hd * dim;
    float s1 = 0.f, s2 = 0.f;
    for (int f = lane; f < dim; f += 32) {
        float v = hp[f];
        s1 += v * a_src[hd * dim + f];
        s2 += v * a_dst[hd * dim + f];
    }
    #pragma unroll
    for (int o = 16; o; o >>= 1) {
        s1 += __shfl_down_sync(0xffffffffu, s1, o);
        s2 += __shfl_down_sync(0xffffffffu, s2, o);
    }
    if (lane == 0) { as[gw] = s1; ad[gw] = s2; }
}

// ---------------- 8: layer-2 gather ----------------
#define CHUNK2 128
__global__ __launch_bounds__(128) void gat_gather2(
    const int* __restrict__ rowptr, const int* __restrict__ csrsrc,
    const float* __restrict__ as, const float* __restrict__ ad,
    const float* __restrict__ h, const float* __restrict__ bias,
    float* __restrict__ out)
{
    int d = blockIdx.x;
    int tid = threadIdx.x;
    int beg = rowptr[d], end = rowptr[d + 1];
    int deg = end - beg;

    __shared__ float ms, dens;
    __shared__ int   s_src[CHUNK2];
    __shared__ float w[CHUNK2];

    float adv = ad[d];
    if (tid == 0) { ms = -INFINITY; dens = 0.f; }
    __syncthreads();

    float acc = 0.f;

    if (deg <= CHUNK2) {
        if (tid < deg) {
            int s = csrsrc[beg + tid];
            s_src[tid] = s;
            float v = as[s] + adv;
            v = v > 0.f ? v : SLOPE * v;
            w[tid] = v;
            atomicMaxF(&ms, v);
        }
        __syncthreads();
        float mv = ms;
        if (tid < deg) {
            float ww = __expf(w[tid] - mv);
            w[tid] = ww;
            atomicAdd(&dens, ww);
        }
        __syncthreads();
        for (int e = 0; e < deg; e++)
            acc += h[(size_t)s_src[e] * OUT2C + tid] * w[e];
    } else {
        for (int t = tid; t < deg; t += 128) {
            float v = as[csrsrc[beg + t]] + adv;
            v = v > 0.f ? v : SLOPE * v;
            atomicMaxF(&ms, v);
        }
        __syncthreads();
        float mv = ms;
        for (int cbeg = 0; cbeg < deg; cbeg += CHUNK2) {
            int clen = min(CHUNK2, deg - cbeg);
            if (tid < clen) {
                int s = csrsrc[beg + cbeg + tid];
                s_src[tid] = s;
                float v = as[s] + adv;
                v = v > 0.f ? v : SLOPE * v;
                float ww = __expf(v - mv);
                w[tid] = ww;
                atomicAdd(&dens, ww);
            }
            __syncthreads();
            for (int e = 0; e < clen; e++)
                acc += h[(size_t)s_src[e] * OUT2C + tid] * w[e];
            __syncthreads();
        }
    }
    __syncthreads();

    float v = acc / (dens + 1e-16f) + bias[tid];
    out[(size_t)d * OUT2C + tid] = v > 0.f ? v : 0.f;
}

// ---------------- 9: gstart ----------------
__global__ void gstart_build(const int* __restrict__ batch, int* __restrict__ gstart) {
    int i = blockIdx.x * blockDim.x + threadIdx.x;
    if (i >= NN) return;
    int b  = batch[i];
    int bp = (i == 0) ? -1 : batch[i - 1];
    for (int g = bp + 1; g <= b; ++g) gstart[g] = i;
    if (i == NN - 1) {
        for (int g = b + 1; g <= GC; ++g) gstart[g] = NN;
    }
}

// ---------------- 10: fused pool(max) + fc + relu ----------------
__global__ __launch_bounds__(128) void pool_fc(
    const float* __restrict__ o2, const int* __restrict__ gstart,
    const float* __restrict__ W, const float* __restrict__ b,
    float* __restrict__ out)
{
    __shared__ float p[OUT2C];
    int g = blockIdx.x, j = threadIdx.x;
    int beg = gstart[g], end = gstart[g + 1];
    float acc = -INFINITY;
    for (int n = beg; n < end; n++)
        acc = fmaxf(acc, o2[(size_t)n * OUT2C + j]);
    p[j] = (beg < end) ? acc : 0.f;
    __syncthreads();
    float s = b[j];
    #pragma unroll 8
    for (int k = 0; k < OUT2C; k++) s += p[k] * W[k * OUT2C + j];
    out[g * OUT2C + j] = s > 0.f ? s : 0.f;
}

// ---------------- 11: cleanup ----------------
__global__ void zero_deg(int* __restrict__ deg) {
    int i = blockIdx.x * blockDim.x + threadIdx.x;
    if (i < NN + 1) deg[i] = 0;
}

// ---------------- launch ----------------
static inline int cdiv(int a, int b) { return (a + b - 1) / b; }

extern "C" void kernel_launch(void* const* d_in, const int* in_sizes, int n_in,
                              void* d_out, int out_size)
{
    const float* x     = (const float*)d_in[0];
    const int*   ei    = (const int*)  d_in[1];
    const int*   batch = (const int*)  d_in[2];
    const float* W1    = (const float*)d_in[4];
    const float* a_s1  = (const float*)d_in[5];
    const float* a_d1  = (const float*)d_in[6];
    const float* b1    = (const float*)d_in[7];
    const float* W2    = (const float*)d_in[8];
    const float* a_s2  = (const float*)d_in[9];
    const float* a_d2  = (const float*)d_in[10];
    const float* b2    = (const float*)d_in[11];
    const float* fcW   = (const float*)d_in[12];
    const float* fcb   = (const float*)d_in[13];
    float* out = (float*)d_out;

    float *agg, *o1, *h2, *o2, *as1, *ad1, *as2, *ad2, *pvec;
    int *deg, *rowptr, *cursor, *csrsrc, *gstart;
    cudaGetSymbolAddress((void**)&agg, g_agg);
    cudaGetSymbolAddress((void**)&o1,  g_o1);
    cudaGetSymbolAddress((void**)&h2,  g_h2);
    cudaGetSymbolAddress((void**)&o2,  g_o2);
    cudaGetSymbolAddress((void**)&as1, g_as1);
    cudaGetSymbolAddress((void**)&ad1, g_ad1);
    cudaGetSymbolAddress((void**)&as2, g_as2);
    cudaGetSymbolAddress((void**)&ad2, g_ad2);
    cudaGetSymbolAddress((void**)&pvec, g_p);
    cudaGetSymbolAddress((void**)&deg,    g_deg);
    cudaGetSymbolAddress((void**)&rowptr, g_rowptr);
    cudaGetSymbolAddress((void**)&cursor, g_cursor);
    cudaGetSymbolAddress((void**)&csrsrc, g_csrsrc);
    cudaGetSymbolAddress((void**)&gstart, g_gstart);

    hist_kernel<<<EDGE_BLOCKS, 256>>>(ei, deg);                              // 1
    scan50k<<<1, 1024>>>(deg, rowptr, cursor, W1, a_s1, a_d1, pvec);         // 2
    csr_scatter_proj<<<EDGE_BLOCKS, 256>>>(ei, cursor, csrsrc, x, pvec, as1, ad1); // 3
    gather1x<<<NN, 256>>>(rowptr, csrsrc, as1, ad1, x, agg);                 // 4 <- ncu
    {
        dim3 grid(cdiv(NN, 128), H1C);
        gemm_head<<<grid, 256>>>(agg, W1, b1, o1);                           // 5
    }
    gemm2_tf32<<<cdiv(NN, 128), 256>>>(o1, W2, h2, NN);                      // 6
    alpha_proj<<<cdiv(NN * 32, 256), 256>>>(h2, a_s2, a_d2, as2, ad2, NN, 1, OUT2C); // 7
    gat_gather2<<<NN, 128>>>(rowptr, csrsrc, as2, ad2, h2, b2, o2);          // 8
    gstart_build<<<cdiv(NN, 256), 256>>>(batch, gstart);                     // 9
    pool_fc<<<GC, OUT2C>>>(o2, gstart, fcW, fcb, out);                       // 10
    zero_deg<<<cdiv(NN + 1, 256), 256>>>(deg);                               // 11
}

// round 13
// speedup vs baseline: 1.4498x; 1.4498x over previous
#include <cuda_runtime.h>
#include <cuda_bf16.h>
#include <cuda_pipeline.h>
#include <mma.h>
#include <math.h>

using namespace nvcuda;

#define NN    50000
#define EE    800000
#define ETOT  (EE + NN)
#define FIN   78
#define H1C   10
#define D1    (H1C * FIN)   // 780
#define OUT2C 128
#define GC    512
#define SLOPE 0.2f
#define CHUNK 64
#define PROJ_BLOCKS ((NN + 31) / 32)       // 1563
#define EDGE_BLOCKS ((ETOT + 255) / 256)   // 3321

// ---------------- scratch ----------------
__device__ float g_agg[(size_t)NN * D1];
__device__ float g_o1 [(size_t)NN * D1];
__device__ float g_h2 [(size_t)NN * OUT2C];
__device__ float g_o2 [(size_t)NN * OUT2C];
__device__ float g_as1[(size_t)NN * H1C];
__device__ float g_ad1[(size_t)NN * H1C];
__device__ float g_as2[NN];
__device__ float g_ad2[NN];
__device__ float g_p  [20 * FIN];
__device__ int   g_deg[NN + 1];            // zero-init; re-zeroed by cleanup
__device__ int   g_rowptr[NN + 1];
__device__ int   g_cursor[NN];
__device__ int   g_csrsrc[ETOT];
__device__ int   g_gstart[GC + 1];

// ---------------- helpers ----------------
__device__ __forceinline__ void atomicMaxF(float* addr, float val) {
    if (!signbit(val)) atomicMax((int*)addr, __float_as_int(val));
    else               atomicMin((unsigned int*)addr, __float_as_uint(val));
}
__device__ __forceinline__ void edge_nodes(const int* __restrict__ ei, int t, int& s, int& d) {
    if (t < EE) { s = ei[t]; d = ei[EE + t]; }
    else        { s = t - EE; d = t - EE; }
}

// ---------------- 1: histogram ----------------
__global__ void hist_kernel(const int* __restrict__ ei, int* __restrict__ deg) {
    int t = blockIdx.x * blockDim.x + threadIdx.x;
    if (t >= ETOT) return;
    int s, d; edge_nodes(ei, t, s, d);
    atomicAdd(&deg[d], 1);
}

// ---------------- 2: scan (shuffle-based) + attention-vector projection -----
__global__ void scan50k(const int* __restrict__ deg, int* __restrict__ rowptr,
                        int* __restrict__ cur,
                        const float* __restrict__ W1, const float* __restrict__ a_src,
                        const float* __restrict__ a_dst, float* __restrict__ p)
{
    for (int idx = threadIdx.x; idx < 20 * FIN; idx += 1024) {
        int o = idx / FIN, k = idx - o * FIN;
        int h = (o < H1C) ? o : o - H1C;
        const float* av = (o < H1C) ? (a_src + h * FIN) : (a_dst + h * FIN);
        const float* wrow = W1 + (size_t)k * D1 + h * FIN;
        float s = 0.f;
        #pragma unroll 13
        for (int f = 0; f < FIN; f++) s += wrow[f] * av[f];
        p[idx] = s;
    }

    __shared__ int warpsum[32];
    __shared__ int carry_s;
    int tid = threadIdx.x, lane = tid & 31, warp = tid >> 5;
    if (tid == 0) carry_s = 0;
    __syncthreads();

    for (int base = 0; base < NN; base += 1024) {
        int i = base + tid;
        int v = (i < NN) ? deg[i] : 0;
        int s = v;
        #pragma unroll
        for (int o = 1; o < 32; o <<= 1) {
            int t = __shfl_up_sync(0xffffffffu, s, o);
            if (lane >= o) s += t;
        }
        if (lane == 31) warpsum[warp] = s;
        __syncthreads();
        if (warp == 0) {
            int ws = warpsum[lane];
            int e = ws;
            #pragma unroll
            for (int o = 1; o < 32; o <<= 1) {
                int t = __shfl_up_sync(0xffffffffu, e, o);
                if (lane >= o) e += t;
            }
            warpsum[lane] = e - ws;   // exclusive warp offset
        }
        __syncthreads();
        int excl = carry_s + warpsum[warp] + s - v;
        if (i < NN) { rowptr[i] = excl; cur[i] = excl; }
        __syncthreads();
        if (tid == 1023) carry_s = excl + v;
        __syncthreads();
    }
    if (threadIdx.x == 0) rowptr[NN] = carry_s;
}

// ---------------- 3: CSR scatter + per-node logits as1/ad1 ------------------
__global__ __launch_bounds__(256) void csr_scatter_proj(
    const int* __restrict__ ei, int* __restrict__ cur, int* __restrict__ csrsrc,
    const float* __restrict__ x, const float* __restrict__ p,
    float* __restrict__ as, float* __restrict__ ad)
{
    int b = blockIdx.x, tid = threadIdx.x;
    int t = b * 256 + tid;
    if (t < ETOT) {
        int s, d; edge_nodes(ei, t, s, d);
        int pos = atomicAdd(&cur[d], 1);
        csrsrc[pos] = s;
    }

    if (b < PROJ_BLOCKS) {
        __shared__ float xs[32][80];
        __shared__ float ps[20][80];
        int nodeBase = b * 32;
        for (int idx = tid; idx < 20 * FIN; idx += 256) {
            int o = idx / FIN, k = idx - o * FIN;
            ps[o][k] = p[idx];
        }
        for (int idx = tid; idx < 32 * FIN; idx += 256) {
            int i = idx / FIN, k = idx - i * FIN;
            int n = nodeBase + i;
            xs[i][k] = (n < NN) ? x[(size_t)n * FIN + k] : 0.f;
        }
        __syncthreads();
        for (int s = tid; s < 32 * 20; s += 256) {
            int i = s / 20, o = s - i * 20;
            int n = nodeBase + i;
            if (n >= NN) continue;
            float acc = 0.f;
            #pragma unroll 13
            for (int k = 0; k < FIN; k++) acc += xs[i][k] * ps[o][k];
            if (o < H1C) as[n * H1C + o] = acc;
            else         ad[n * H1C + (o - H1C)] = acc;
        }
    }
}

// ---------------- 4: layer-1 gather (R8 structure, float2 staging) ----------
// accumulate: 200 active threads, hh = tid/20, f4 = (tid%20)*4
__global__ __launch_bounds__(256) void gather1x(
    const int* __restrict__ rowptr, const int* __restrict__ csrsrc,
    const float* __restrict__ as, const float* __restrict__ ad,
    const float* __restrict__ x, float* __restrict__ agg)
{
    int d = blockIdx.x;
    int tid = threadIdx.x;
    int beg = rowptr[d], end = rowptr[d + 1];
    int deg = end - beg;

    __shared__ float m[H1C];
    __shared__ float den[H1C];
    __shared__ float adv[H1C];
    __shared__ int   s_src[CHUNK];
    __shared__ float w[CHUNK][H1C];
    __shared__ __align__(16) float xs[CHUNK][80];

    if (tid < H1C) {
        adv[tid] = ad[d * H1C + tid];
        m[tid] = -INFINITY;
        den[tid] = 0.f;
    }
    __syncthreads();

    const bool active = tid < 200;
    int hh = tid / 20;
    int f4 = (tid % 20) * 4;
    float a0 = 0.f, a1 = 0.f, a2 = 0.f, a3 = 0.f;

    if (deg <= CHUNK) {
        for (int t = tid; t < deg; t += 256) s_src[t] = csrsrc[beg + t];
        __syncthreads();
        // float2 staging: 40 pairs per edge (39 data + 1 pad-zero slot)
        for (int t = tid; t < deg * 40; t += 256) {
            int e = t / 40, kp = t - e * 40;
            if (kp < 39)
                *(float2*)&xs[e][kp * 2] =
                    *(const float2*)(x + (size_t)s_src[e] * FIN + kp * 2);
            else { xs[e][78] = 0.f; xs[e][79] = 0.f; }
        }
        // logits (distributed over 256 threads, R8-proven)
        for (int t = tid; t < deg * H1C; t += 256) {
            int e = t / H1C, h = t - e * H1C;
            float v = as[s_src[e] * H1C + h] + adv[h];
            v = v > 0.f ? v : SLOPE * v;
            w[e][h] = v;
            atomicMaxF(&m[h], v);
        }
        __syncthreads();
        for (int t = tid; t < deg * H1C; t += 256) {
            int e = t / H1C, h = t - e * H1C;
            float ww = __expf(w[e][h] - m[h]);
            w[e][h] = ww;
            atomicAdd(&den[h], ww);
        }
        __syncthreads();
        if (active) {
            for (int e = 0; e < deg; e++) {
                float4 xv = *(const float4*)&xs[e][f4];
                float ww = w[e][hh];
                a0 += xv.x * ww; a1 += xv.y * ww; a2 += xv.z * ww; a3 += xv.w * ww;
            }
        }
    } else {
        // max pass over all edges (distributed)
        for (int t = tid; t < deg * H1C; t += 256) {
            int e = t / H1C, h = t - e * H1C;
            int s = csrsrc[beg + e];
            float v = as[s * H1C + h] + adv[h];
            v = v > 0.f ? v : SLOPE * v;
            atomicMaxF(&m[h], v);
        }
        __syncthreads();
        for (int cbeg = 0; cbeg < deg; cbeg += CHUNK) {
            int clen = min(CHUNK, deg - cbeg);
            for (int t = tid; t < clen; t += 256) s_src[t] = csrsrc[beg + cbeg + t];
            __syncthreads();
            for (int t = tid; t < clen * 40; t += 256) {
                int e = t / 40, kp = t - e * 40;
                if (kp < 39)
                    *(float2*)&xs[e][kp * 2] =
                        *(const float2*)(x + (size_t)s_src[e] * FIN + kp * 2);
                else { xs[e][78] = 0.f; xs[e][79] = 0.f; }
            }
            for (int t = tid; t < clen * H1C; t += 256) {
                int e = t / H1C, h = t - e * H1C;
                float v = as[s_src[e] * H1C + h] + adv[h];
                v = v > 0.f ? v : SLOPE * v;
                float ww = __expf(v - m[h]);
                w[e][h] = ww;
                atomicAdd(&den[h], ww);
            }
            __syncthreads();
            if (active) {
                for (int e = 0; e < clen; e++) {
                    float4 xv = *(const float4*)&xs[e][f4];
                    float ww = w[e][hh];
                    a0 += xv.x * ww; a1 += xv.y * ww; a2 += xv.z * ww; a3 += xv.w * ww;
                }
            }
            __syncthreads();
        }
    }
    __syncthreads();

    if (active) {
        float inv = 1.f / (den[hh] + 1e-16f);
        float* op = agg + (size_t)d * D1 + hh * FIN + f4;
        op[0] = a0 * inv;
        if (f4 + 1 < FIN) op[1] = a1 * inv;
        if (f4 + 2 < FIN) op[2] = a2 * inv;
        if (f4 + 3 < FIN) op[3] = a3 * inv;
    }
}

// ---------------- 5: block-diagonal GEMM + bias + relu ----------------------
#define BK1 26
__global__ __launch_bounds__(256) void gemm_head(
    const float* __restrict__ agg, const float* __restrict__ W1,
    const float* __restrict__ b1, float* __restrict__ out1)
{
    __shared__ float As[BK1][128];
    __shared__ float Bs[BK1][80];
    int h = blockIdx.y;
    int rowBase = blockIdx.x * 128;
    int tid = threadIdx.x;
    int ty = tid >> 3;
    int tx = tid & 7;
    int r0 = ty * 4;

    float acc[4][10] = {};

    for (int k0 = 0; k0 < FIN; k0 += BK1) {
        for (int idx = tid; idx < 128 * BK1; idx += 256) {
            int r = idx / BK1, c = idx - r * BK1;
            int gr = rowBase + r;
            As[c][r] = (gr < NN) ? agg[(size_t)gr * D1 + h * FIN + k0 + c] : 0.f;
        }
        for (int idx = tid; idx < BK1 * FIN; idx += 256) {
            int r = idx / FIN, c = idx - r * FIN;
            Bs[r][c] = W1[(size_t)(k0 + r) * D1 + h * FIN + c];
        }
        __syncthreads();
        #pragma unroll
        for (int k = 0; k < BK1; k++) {
            float a0 = As[k][r0], a1 = As[k][r0 + 1], a2 = As[k][r0 + 2], a3 = As[k][r0 + 3];
            float b[10];
            #pragma unroll
            for (int j = 0; j < 10; j++) b[j] = Bs[k][tx * 10 + j];
            #pragma unroll
            for (int j = 0; j < 10; j++) {
                acc[0][j] += a0 * b[j];
                acc[1][j] += a1 * b[j];
                acc[2][j] += a2 * b[j];
                acc[3][j] += a3 * b[j];
            }
        }
        __syncthreads();
    }

    #pragma unroll
    for (int i = 0; i < 4; i++) {
        int gr = rowBase + r0 + i;
        if (gr >= NN) continue;
        #pragma unroll
        for (int j = 0; j < 10; j++) {
            int gc = tx * 10 + j;
            if (gc < FIN) {
                float v = acc[i][j] + b1[h * FIN + gc];
                out1[(size_t)gr * D1 + h * FIN + gc] = v > 0.f ? v : 0.f;
            }
        }
    }
}

// ---------------- 6: layer-2 GEMM, TF32 tensor cores, cp.async pipeline -----
#define K2    780
#define NCH   49
#define LDAS  20
#define LDBS  136

__global__ __launch_bounds__(256) void gemm2_tf32(
    const float* __restrict__ A, const float* __restrict__ B, float* __restrict__ C, int M)
{
    __shared__ float As[2][128][LDAS];
    __shared__ float Bs[2][16][LDBS];

    int tid = threadIdx.x;
    int warp = tid >> 5;
    int warp_m = warp & 3;
    int warp_n = warp >> 2;
    int rowBase = blockIdx.x * 128;

    wmma::fragment<wmma::accumulator, 16, 16, 8, float> acc[2][4];
    #pragma unroll
    for (int i = 0; i < 2; i++)
        #pragma unroll
        for (int j = 0; j < 4; j++) wmma::fill_fragment(acc[i][j], 0.f);

    auto load_stage = [&](int ch, int buf) {
        int k0 = ch * 16;
        #pragma unroll
        for (int l = 0; l < 2; l++) {
            int idx = tid + l * 256;
            int r = idx >> 2, c4 = idx & 3;
            int gr = rowBase + r;
            int gk = k0 + c4 * 4;
            bool valid = (gr < M) && (gk < K2);
            const float* src = A + (size_t)gr * K2 + gk;
            __pipeline_memcpy_async(&As[buf][r][c4 * 4], src, 16, valid ? 0 : 16);
        }
        #pragma unroll
        for (int l = 0; l < 2; l++) {
            int idx = tid + l * 256;
            int r = idx >> 5, c = idx & 31;
            int gk = k0 + r;
            bool valid = (gk < K2);
            const float* src = B + (size_t)gk * OUT2C + c * 4;
            __pipeline_memcpy_async(&Bs[buf][r][c * 4], src, 16, valid ? 0 : 16);
        }
        __pipeline_commit();
    };

    load_stage(0, 0);

    for (int ch = 0; ch < NCH; ch++) {
        int buf = ch & 1;
        if (ch + 1 < NCH) load_stage(ch + 1, (ch + 1) & 1);
        __pipeline_wait_prior((ch + 1 < NCH) ? 1 : 0);
        __syncthreads();

        #pragma unroll
        for (int kk = 0; kk < 16; kk += 8) {
            wmma::fragment<wmma::matrix_a, 16, 16, 8, wmma::precision::tf32, wmma::row_major> af[2];
            wmma::fragment<wmma::matrix_b, 16, 16, 8, wmma::precision::tf32, wmma::row_major> bf[4];
            #pragma unroll
            for (int i = 0; i < 2; i++) {
                wmma::load_matrix_sync(af[i], &As[buf][warp_m * 32 + i * 16][kk], LDAS);
                #pragma unroll
                for (int t = 0; t < af[i].num_elements; t++)
                    af[i].x[t] = wmma::__float_to_tf32(af[i].x[t]);
            }
            #pragma unroll
            for (int j = 0; j < 4; j++) {
                wmma::load_matrix_sync(bf[j], &Bs[buf][kk][warp_n * 64 + j * 16], LDBS);
                #pragma unroll
                for (int t = 0; t < bf[j].num_elements; t++)
                    bf[j].x[t] = wmma::__float_to_tf32(bf[j].x[t]);
            }
            #pragma unroll
            for (int i = 0; i < 2; i++)
                #pragma unroll
                for (int j = 0; j < 4; j++)
                    wmma::mma_sync(acc[i][j], af[i], bf[j], acc[i][j]);
        }
        __syncthreads();
    }

    #pragma unroll
    for (int i = 0; i < 2; i++) {
        int gr = rowBase + warp_m * 32 + i * 16;
        if (gr >= M) continue;
        #pragma unroll
        for (int j = 0; j < 4; j++) {
            int gc = warp_n * 64 + j * 16;
            wmma::store_matrix_sync(&C[(size_t)gr * OUT2C + gc], acc[i][j], OUT2C, wmma::mem_row_major);
        }
    }
}

// ---------------- 7: layer-2 attention projections --------------------------
__global__ void alpha_proj(const float* __restrict__ h,
                           const float* __restrict__ a_src, const float* __restrict__ a_dst,
                           float* __restrict__ as, float* __restrict__ ad,
                           int n, int heads, int dim)
{
    int gw = (blockIdx.x * blockDim.x + threadIdx.x) >> 5;
    int lane = threadIdx.x & 31;
    if (gw >= n * heads) return;
    int node = gw / heads, hd = gw - node * heads;
    const float* hp = h + (size_t)node * heads * dim + (size_t)hd * dim;
    float s1 = 0.f, s2 = 0.f;
    for (int f = lane; f < dim; f += 32) {
        float v = hp[f];
        s1 += v * a_src[hd * dim + f];
        s2 += v * a_dst[hd * dim + f];
    }
    #pragma unroll
    for (int o = 16; o; o >>= 1) {
        s1 += __shfl_down_sync(0xffffffffu, s1, o);
        s2 += __shfl_down_sync(0xffffffffu, s2, o);
    }
    if (lane == 0) { as[gw] = s1; ad[gw] = s2; }
}

// ---------------- 8: layer-2 gather ----------------
#define CHUNK2 128
__global__ __launch_bounds__(128) void gat_gather2(
    const int* __restrict__ rowptr, const int* __restrict__ csrsrc,
    const float* __restrict__ as, const float* __restrict__ ad,
    const float* __restrict__ h, const float* __restrict__ bias,
    float* __restrict__ out)
{
    int d = blockIdx.x;
    int tid = threadIdx.x;
    int beg = rowptr[d], end = rowptr[d + 1];
    int deg = end - beg;

    __shared__ float ms, dens;
    __shared__ int   s_src[CHUNK2];
    __shared__ float w[CHUNK2];

    float adv = ad[d];
    if (tid == 0) { ms = -INFINITY; dens = 0.f; }
    __syncthreads();

    float acc = 0.f;

    if (deg <= CHUNK2) {
        if (tid < deg) {
            int s = csrsrc[beg + tid];
            s_src[tid] = s;
            float v = as[s] + adv;
            v = v > 0.f ? v : SLOPE * v;
            w[tid] = v;
            atomicMaxF(&ms, v);
        }
        __syncthreads();
        float mv = ms;
        if (tid < deg) {
            float ww = __expf(w[tid] - mv);
            w[tid] = ww;
            atomicAdd(&dens, ww);
        }
        __syncthreads();
        for (int e = 0; e < deg; e++)
            acc += h[(size_t)s_src[e] * OUT2C + tid] * w[e];
    } else {
        for (int t = tid; t < deg; t += 128) {
            float v = as[csrsrc[beg + t]] + adv;
            v = v > 0.f ? v : SLOPE * v;
            atomicMaxF(&ms, v);
        }
        __syncthreads();
        float mv = ms;
        for (int cbeg = 0; cbeg < deg; cbeg += CHUNK2) {
            int clen = min(CHUNK2, deg - cbeg);
            if (tid < clen) {
                int s = csrsrc[beg + cbeg + tid];
                s_src[tid] = s;
                float v = as[s] + adv;
                v = v > 0.f ? v : SLOPE * v;
                float ww = __expf(v - mv);
                w[tid] = ww;
                atomicAdd(&dens, ww);
            }
            __syncthreads();
            for (int e = 0; e < clen; e++)
                acc += h[(size_t)s_src[e] * OUT2C + tid] * w[e];
            __syncthreads();
        }
    }
    __syncthreads();

    float v = acc / (dens + 1e-16f) + bias[tid];
    out[(size_t)d * OUT2C + tid] = v > 0.f ? v : 0.f;
}

// ---------------- 9: gstart ----------------
__global__ void gstart_build(const int* __restrict__ batch, int* __restrict__ gstart) {
    int i = blockIdx.x * blockDim.x + threadIdx.x;
    if (i >= NN) return;
    int b  = batch[i];
    int bp = (i == 0) ? -1 : batch[i - 1];
    for (int g = bp + 1; g <= b; ++g) gstart[g] = i;
    if (i == NN - 1) {
        for (int g = b + 1; g <= GC; ++g) gstart[g] = NN;
    }
}

// ---------------- 10: fused pool(max) + fc + relu ----------------
__global__ __launch_bounds__(128) void pool_fc(
    const float* __restrict__ o2, const int* __restrict__ gstart,
    const float* __restrict__ W, const float* __restrict__ b,
    float* __restrict__ out)
{
    __shared__ float p[OUT2C];
    int g = blockIdx.x, j = threadIdx.x;
    int beg = gstart[g], end = gstart[g + 1];
    float acc = -INFINITY;
    for (int n = beg; n < end; n++)
        acc = fmaxf(acc, o2[(size_t)n * OUT2C + j]);
    p[j] = (beg < end) ? acc : 0.f;
    __syncthreads();
    float s = b[j];
    #pragma unroll 8
    for (int k = 0; k < OUT2C; k++) s += p[k] * W[k * OUT2C + j];
    out[g * OUT2C + j] = s > 0.f ? s : 0.f;
}

// ---------------- 11: cleanup ----------------
__global__ void zero_deg(int* __restrict__ deg) {
    int i = blockIdx.x * blockDim.x + threadIdx.x;
    if (i < NN + 1) deg[i] = 0;
}

// ---------------- launch ----------------
static inline int cdiv(int a, int b) { return (a + b - 1) / b; }

extern "C" void kernel_launch(void* const* d_in, const int* in_sizes, int n_in,
                              void* d_out, int out_size)
{
    const float* x     = (const float*)d_in[0];
    const int*   ei    = (const int*)  d_in[1];
    const int*   batch = (const int*)  d_in[2];
    const float* W1    = (const float*)d_in[4];
    const float* a_s1  = (const float*)d_in[5];
    const float* a_d1  = (const float*)d_in[6];
    const float* b1    = (const float*)d_in[7];
    const float* W2    = (const float*)d_in[8];
    const float* a_s2  = (const float*)d_in[9];
    const float* a_d2  = (const float*)d_in[10];
    const float* b2    = (const float*)d_in[11];
    const float* fcW   = (const float*)d_in[12];
    const float* fcb   = (const float*)d_in[13];
    float* out = (float*)d_out;

    float *agg, *o1, *h2, *o2, *as1, *ad1, *as2, *ad2, *pvec;
    int *deg, *rowptr, *cursor, *csrsrc, *gstart;
    cudaGetSymbolAddress((void**)&agg, g_agg);
    cudaGetSymbolAddress((void**)&o1,  g_o1);
    cudaGetSymbolAddress((void**)&h2,  g_h2);
    cudaGetSymbolAddress((void**)&o2,  g_o2);
    cudaGetSymbolAddress((void**)&as1, g_as1);
    cudaGetSymbolAddress((void**)&ad1, g_ad1);
    cudaGetSymbolAddress((void**)&as2, g_as2);
    cudaGetSymbolAddress((void**)&ad2, g_ad2);
    cudaGetSymbolAddress((void**)&pvec, g_p);
    cudaGetSymbolAddress((void**)&deg,    g_deg);
    cudaGetSymbolAddress((void**)&rowptr, g_rowptr);
    cudaGetSymbolAddress((void**)&cursor, g_cursor);
    cudaGetSymbolAddress((void**)&csrsrc, g_csrsrc);
    cudaGetSymbolAddress((void**)&gstart, g_gstart);

    hist_kernel<<<EDGE_BLOCKS, 256>>>(ei, deg);                              // 1
    scan50k<<<1, 1024>>>(deg, rowptr, cursor, W1, a_s1, a_d1, pvec);         // 2
    csr_scatter_proj<<<EDGE_BLOCKS, 256>>>(ei, cursor, csrsrc, x, pvec, as1, ad1); // 3
    gather1x<<<NN, 256>>>(rowptr, csrsrc, as1, ad1, x, agg);                 // 4 <- ncu
    {
        dim3 grid(cdiv(NN, 128), H1C);
        gemm_head<<<grid, 256>>>(agg, W1, b1, o1);                           // 5
    }
    gemm2_tf32<<<cdiv(NN, 128), 256>>>(o1, W2, h2, NN);                      // 6
    alpha_proj<<<cdiv(NN * 32, 256), 256>>>(h2, a_s2, a_d2, as2, ad2, NN, 1, OUT2C); // 7
    gat_gather2<<<NN, 128>>>(rowptr, csrsrc, as2, ad2, h2, b2, o2);          // 8
    gstart_build<<<cdiv(NN, 256), 256>>>(batch, gstart);                     // 9
    pool_fc<<<GC, OUT2C>>>(o2, gstart, fcW, fcb, out);                       // 10
    zero_deg<<<cdiv(NN + 1, 256), 256>>>(deg);                               // 11
}

// round 15
// speedup vs baseline: 1.6744x; 1.1549x over previous
#include <cuda_runtime.h>
#include <cuda_bf16.h>
#include <cuda_pipeline.h>
#include <mma.h>
#include <math.h>

using namespace nvcuda;

#define NN    50000
#define EE    800000
#define ETOT  (EE + NN)
#define FIN   78
#define H1C   10
#define D1    (H1C * FIN)   // 780
#define OUT2C 128
#define GC    512
#define SLOPE 0.2f
#define CHUNK 64
#define PROJ_BLOCKS ((NN + 31) / 32)       // 1563
#define EDGE_BLOCKS ((ETOT + 255) / 256)   // 3321

// ---------------- scratch ----------------
__device__ float g_agg[(size_t)NN * D1];
__device__ float g_o1 [(size_t)NN * D1];
__device__ float g_h2 [(size_t)NN * OUT2C];
__device__ float g_o2 [(size_t)NN * OUT2C];
__device__ float g_as1[(size_t)NN * H1C];
__device__ float g_ad1[(size_t)NN * H1C];
__device__ float g_as2[NN];
__device__ float g_ad2[NN];
__device__ float g_p  [20 * FIN];
__device__ int   g_deg[NN + 1];            // zero-init; re-zeroed by cleanup
__device__ int   g_rowptr[NN + 1];
__device__ int   g_cursor[NN];
__device__ int   g_csrsrc[ETOT];
__device__ int   g_gstart[GC + 1];

// ---------------- helpers ----------------
__device__ __forceinline__ void atomicMaxF(float* addr, float val) {
    if (!signbit(val)) atomicMax((int*)addr, __float_as_int(val));
    else               atomicMin((unsigned int*)addr, __float_as_uint(val));
}
__device__ __forceinline__ void edge_nodes(const int* __restrict__ ei, int t, int& s, int& d) {
    if (t < EE) { s = ei[t]; d = ei[EE + t]; }
    else        { s = t - EE; d = t - EE; }
}

// ---------------- 1: histogram ----------------
__global__ void hist_kernel(const int* __restrict__ ei, int* __restrict__ deg) {
    int t = blockIdx.x * blockDim.x + threadIdx.x;
    if (t >= ETOT) return;
    int s, d; edge_nodes(ei, t, s, d);
    atomicAdd(&deg[d], 1);
}

// ---------------- 2: scan (shuffle-based) + attention-vector projection -----
__global__ void scan50k(const int* __restrict__ deg, int* __restrict__ rowptr,
                        int* __restrict__ cur,
                        const float* __restrict__ W1, const float* __restrict__ a_src,
                        const float* __restrict__ a_dst, float* __restrict__ p)
{
    for (int idx = threadIdx.x; idx < 20 * FIN; idx += 1024) {
        int o = idx / FIN, k = idx - o * FIN;
        int h = (o < H1C) ? o : o - H1C;
        const float* av = (o < H1C) ? (a_src + h * FIN) : (a_dst + h * FIN);
        const float* wrow = W1 + (size_t)k * D1 + h * FIN;
        float s = 0.f;
        #pragma unroll 13
        for (int f = 0; f < FIN; f++) s += wrow[f] * av[f];
        p[idx] = s;
    }

    __shared__ int warpsum[32];
    __shared__ int carry_s;
    int tid = threadIdx.x, lane = tid & 31, warp = tid >> 5;
    if (tid == 0) carry_s = 0;
    __syncthreads();

    for (int base = 0; base < NN; base += 1024) {
        int i = base + tid;
        int v = (i < NN) ? deg[i] : 0;
        int s = v;
        #pragma unroll
        for (int o = 1; o < 32; o <<= 1) {
            int t = __shfl_up_sync(0xffffffffu, s, o);
            if (lane >= o) s += t;
        }
        if (lane == 31) warpsum[warp] = s;
        __syncthreads();
        if (warp == 0) {
            int ws = warpsum[lane];
            int e = ws;
            #pragma unroll
            for (int o = 1; o < 32; o <<= 1) {
                int t = __shfl_up_sync(0xffffffffu, e, o);
                if (lane >= o) e += t;
            }
            warpsum[lane] = e - ws;   // exclusive warp offset
        }
        __syncthreads();
        int excl = carry_s + warpsum[warp] + s - v;
        if (i < NN) { rowptr[i] = excl; cur[i] = excl; }
        __syncthreads();
        if (tid == 1023) carry_s = excl + v;
        __syncthreads();
    }
    if (threadIdx.x == 0) rowptr[NN] = carry_s;
}

// ---------------- 3: CSR scatter + per-node logits as1/ad1 ------------------
__global__ __launch_bounds__(256) void csr_scatter_proj(
    const int* __restrict__ ei, int* __restrict__ cur, int* __restrict__ csrsrc,
    const float* __restrict__ x, const float* __restrict__ p,
    float* __restrict__ as, float* __restrict__ ad)
{
    int b = blockIdx.x, tid = threadIdx.x;
    int t = b * 256 + tid;
    if (t < ETOT) {
        int s, d; edge_nodes(ei, t, s, d);
        int pos = atomicAdd(&cur[d], 1);
        csrsrc[pos] = s;
    }

    if (b < PROJ_BLOCKS) {
        __shared__ float xs[32][80];
        __shared__ float ps[20][80];
        int nodeBase = b * 32;
        for (int idx = tid; idx < 20 * FIN; idx += 256) {
            int o = idx / FIN, k = idx - o * FIN;
            ps[o][k] = p[idx];
        }
        for (int idx = tid; idx < 32 * FIN; idx += 256) {
            int i = idx / FIN, k = idx - i * FIN;
            int n = nodeBase + i;
            xs[i][k] = (n < NN) ? x[(size_t)n * FIN + k] : 0.f;
        }
        __syncthreads();
        for (int s = tid; s < 32 * 20; s += 256) {
            int i = s / 20, o = s - i * 20;
            int n = nodeBase + i;
            if (n >= NN) continue;
            float acc = 0.f;
            #pragma unroll 13
            for (int k = 0; k < FIN; k++) acc += xs[i][k] * ps[o][k];
            if (o < H1C) as[n * H1C + o] = acc;
            else         ad[n * H1C + (o - H1C)] = acc;
        }
    }
}

// ---------------- 4: layer-1 gather (R12-proven) ----------------------------
__global__ __launch_bounds__(256) void gather1x(
    const int* __restrict__ rowptr, const int* __restrict__ csrsrc,
    const float* __restrict__ as, const float* __restrict__ ad,
    const float* __restrict__ x, float* __restrict__ agg)
{
    int d = blockIdx.x;
    int tid = threadIdx.x;
    int beg = rowptr[d], end = rowptr[d + 1];
    int deg = end - beg;

    __shared__ float m[H1C];
    __shared__ float den[H1C];
    __shared__ float adv[H1C];
    __shared__ int   s_src[CHUNK];
    __shared__ float w[CHUNK][H1C];
    __shared__ __align__(16) float xs[CHUNK][80];

    if (tid < H1C) {
        adv[tid] = ad[d * H1C + tid];
        m[tid] = -INFINITY;
        den[tid] = 0.f;
    }
    __syncthreads();

    const bool active = tid < 200;
    int hh = tid / 20;
    int f4 = (tid % 20) * 4;
    float a0 = 0.f, a1 = 0.f, a2 = 0.f, a3 = 0.f;

    if (deg <= CHUNK) {
        for (int t = tid; t < deg; t += 256) s_src[t] = csrsrc[beg + t];
        __syncthreads();
        for (int t = tid; t < deg * 40; t += 256) {
            int e = t / 40, kp = t - e * 40;
            if (kp < 39)
                *(float2*)&xs[e][kp * 2] =
                    *(const float2*)(x + (size_t)s_src[e] * FIN + kp * 2);
            else { xs[e][78] = 0.f; xs[e][79] = 0.f; }
        }
        for (int t = tid; t < deg * H1C; t += 256) {
            int e = t / H1C, h = t - e * H1C;
            float v = as[s_src[e] * H1C + h] + adv[h];
            v = v > 0.f ? v : SLOPE * v;
            w[e][h] = v;
            atomicMaxF(&m[h], v);
        }
        __syncthreads();
        for (int t = tid; t < deg * H1C; t += 256) {
            int e = t / H1C, h = t - e * H1C;
            float ww = __expf(w[e][h] - m[h]);
            w[e][h] = ww;
            atomicAdd(&den[h], ww);
        }
        __syncthreads();
        if (active) {
            for (int e = 0; e < deg; e++) {
                float4 xv = *(const float4*)&xs[e][f4];
                float ww = w[e][hh];
                a0 += xv.x * ww; a1 += xv.y * ww; a2 += xv.z * ww; a3 += xv.w * ww;
            }
        }
    } else {
        for (int t = tid; t < deg * H1C; t += 256) {
            int e = t / H1C, h = t - e * H1C;
            int s = csrsrc[beg + e];
            float v = as[s * H1C + h] + adv[h];
            v = v > 0.f ? v : SLOPE * v;
            atomicMaxF(&m[h], v);
        }
        __syncthreads();
        for (int cbeg = 0; cbeg < deg; cbeg += CHUNK) {
            int clen = min(CHUNK, deg - cbeg);
            for (int t = tid; t < clen; t += 256) s_src[t] = csrsrc[beg + cbeg + t];
            __syncthreads();
            for (int t = tid; t < clen * 40; t += 256) {
                int e = t / 40, kp = t - e * 40;
                if (kp < 39)
                    *(float2*)&xs[e][kp * 2] =
                        *(const float2*)(x + (size_t)s_src[e] * FIN + kp * 2);
                else { xs[e][78] = 0.f; xs[e][79] = 0.f; }
            }
            for (int t = tid; t < clen * H1C; t += 256) {
                int e = t / H1C, h = t - e * H1C;
                float v = as[s_src[e] * H1C + h] + adv[h];
                v = v > 0.f ? v : SLOPE * v;
                float ww = __expf(v - m[h]);
                w[e][h] = ww;
                atomicAdd(&den[h], ww);
            }
            __syncthreads();
            if (active) {
                for (int e = 0; e < clen; e++) {
                    float4 xv = *(const float4*)&xs[e][f4];
                    float ww = w[e][hh];
                    a0 += xv.x * ww; a1 += xv.y * ww; a2 += xv.z * ww; a3 += xv.w * ww;
                }
            }
            __syncthreads();
        }
    }
    __syncthreads();

    if (active) {
        float inv = 1.f / (den[hh] + 1e-16f);
        float* op = agg + (size_t)d * D1 + hh * FIN + f4;
        op[0] = a0 * inv;
        if (f4 + 1 < FIN) op[1] = a1 * inv;
        if (f4 + 2 < FIN) op[2] = a2 * inv;
        if (f4 + 3 < FIN) op[3] = a3 * inv;
    }
}

// ---------------- 5: per-head TF32 GEMM + bias + relu -----------------------
// o1[n, h*78+c] = relu(sum_k agg[n, h*78+k]*W1[k, h*78+c] + b1[h*78+c])
// Block: 128 rows x one head. 8 warps: warp = 16-row strip, 5 N-frags (80 pad).
#define LDA1 20    // 16 + 4
#define LDB1 88    // 80 + 8
#define LDC1 84    // 80 + 4
__global__ __launch_bounds__(256) void gemm1h_tf32(
    const float* __restrict__ agg, const float* __restrict__ W1,
    const float* __restrict__ b1, float* __restrict__ o1)
{
    __shared__ __align__(16) float As[128][LDA1];   // 10240 B
    __shared__ __align__(16) float Bs[16][LDB1];    //  5632 B
    __shared__ __align__(16) float Cs[64][LDC1];    // 21504 B  (total ~37.4 KB)

    int h = blockIdx.y;
    int rowBase = blockIdx.x * 128;
    int tid = threadIdx.x;
    int warp = tid >> 5;
    const float* Abase = agg + (size_t)0 * D1 + h * FIN;
    const float* Bbase = W1 + h * FIN;

    wmma::fragment<wmma::accumulator, 16, 16, 8, float> acc[5];
    #pragma unroll
    for (int j = 0; j < 5; j++) wmma::fill_fragment(acc[j], 0.f);

    for (int k0 = 0; k0 < FIN; k0 += 16) {
        // A chunk: 128 rows x 16 K-floats = 1024 float2
        #pragma unroll
        for (int l = 0; l < 4; l++) {
            int idx = tid + l * 256;
            int r = idx >> 3, pr = idx & 7;
            int gk = k0 + pr * 2;
            int gr = rowBase + r;
            float2 v = make_float2(0.f, 0.f);
            if (gr < NN && gk < FIN)
                v = *(const float2*)(Abase + (size_t)gr * D1 + gk);
            *(float2*)&As[r][pr * 2] = v;
        }
        // B chunk: 16 K-rows x 80 cols = 640 float2
        for (int idx = tid; idx < 640; idx += 256) {
            int r = idx / 40, pc = idx % 40;
            int gk = k0 + r, gc = pc * 2;
            float2 v = make_float2(0.f, 0.f);
            if (gk < FIN && gc < FIN)
                v = *(const float2*)(Bbase + (size_t)gk * D1 + gc);
            *(float2*)&Bs[r][pc * 2] = v;
        }
        __syncthreads();

        #pragma unroll
        for (int kk = 0; kk < 16; kk += 8) {
            wmma::fragment<wmma::matrix_a, 16, 16, 8, wmma::precision::tf32, wmma::row_major> af;
            wmma::load_matrix_sync(af, &As[warp * 16][kk], LDA1);
            #pragma unroll
            for (int t = 0; t < af.num_elements; t++) af.x[t] = wmma::__float_to_tf32(af.x[t]);
            #pragma unroll
            for (int j = 0; j < 5; j++) {
                wmma::fragment<wmma::matrix_b, 16, 16, 8, wmma::precision::tf32, wmma::row_major> bf;
                wmma::load_matrix_sync(bf, &Bs[kk][j * 16], LDB1);
                #pragma unroll
                for (int t = 0; t < bf.num_elements; t++) bf.x[t] = wmma::__float_to_tf32(bf.x[t]);
                wmma::mma_sync(acc[j], af, bf, acc[j]);
            }
        }
        __syncthreads();
    }

    // epilogue: two phases through 64-row staging, bias+relu on copy-out
    for (int p = 0; p < 2; p++) {
        if (warp >= p * 4 && warp < p * 4 + 4) {
            int lr = (warp - p * 4) * 16;
            #pragma unroll
            for (int j = 0; j < 5; j++)
                wmma::store_matrix_sync(&Cs[lr][j * 16], acc[j], LDC1, wmma::mem_row_major);
        }
        __syncthreads();
        for (int idx = tid; idx < 64 * FIN; idx += 256) {
            int r = idx / FIN, c = idx - r * FIN;
            int gr = rowBase + p * 64 + r;
            if (gr < NN) {
                float v = Cs[r][c] + b1[h * FIN + c];
                o1[(size_t)gr * D1 + h * FIN + c] = v > 0.f ? v : 0.f;
            }
        }
        __syncthreads();
    }
}

// ---------------- 6: layer-2 GEMM, TF32 tensor cores, cp.async pipeline -----
#define K2    780
#define NCH   49
#define LDAS  20
#define LDBS  136

__global__ __launch_bounds__(256) void gemm2_tf32(
    const float* __restrict__ A, const float* __restrict__ B, float* __restrict__ C, int M)
{
    __shared__ float As[2][128][LDAS];
    __shared__ float Bs[2][16][LDBS];

    int tid = threadIdx.x;
    int warp = tid >> 5;
    int warp_m = warp & 3;
    int warp_n = warp >> 2;
    int rowBase = blockIdx.x * 128;

    wmma::fragment<wmma::accumulator, 16, 16, 8, float> acc[2][4];
    #pragma unroll
    for (int i = 0; i < 2; i++)
        #pragma unroll
        for (int j = 0; j < 4; j++) wmma::fill_fragment(acc[i][j], 0.f);

    auto load_stage = [&](int ch, int buf) {
        int k0 = ch * 16;
        #pragma unroll
        for (int l = 0; l < 2; l++) {
            int idx = tid + l * 256;
            int r = idx >> 2, c4 = idx & 3;
            int gr = rowBase + r;
            int gk = k0 + c4 * 4;
            bool valid = (gr < M) && (gk < K2);
            const float* src = A + (size_t)gr * K2 + gk;
            __pipeline_memcpy_async(&As[buf][r][c4 * 4], src, 16, valid ? 0 : 16);
        }
        #pragma unroll
        for (int l = 0; l < 2; l++) {
            int idx = tid + l * 256;
            int r = idx >> 5, c = idx & 31;
            int gk = k0 + r;
            bool valid = (gk < K2);
            const float* src = B + (size_t)gk * OUT2C + c * 4;
            __pipeline_memcpy_async(&Bs[buf][r][c * 4], src, 16, valid ? 0 : 16);
        }
        __pipeline_commit();
    };

    load_stage(0, 0);

    for (int ch = 0; ch < NCH; ch++) {
        int buf = ch & 1;
        if (ch + 1 < NCH) load_stage(ch + 1, (ch + 1) & 1);
        __pipeline_wait_prior((ch + 1 < NCH) ? 1 : 0);
        __syncthreads();

        #pragma unroll
        for (int kk = 0; kk < 16; kk += 8) {
            wmma::fragment<wmma::matrix_a, 16, 16, 8, wmma::precision::tf32, wmma::row_major> af[2];
            wmma::fragment<wmma::matrix_b, 16, 16, 8, wmma::precision::tf32, wmma::row_major> bf[4];
            #pragma unroll
            for (int i = 0; i < 2; i++) {
                wmma::load_matrix_sync(af[i], &As[buf][warp_m * 32 + i * 16][kk], LDAS);
                #pragma unroll
                for (int t = 0; t < af[i].num_elements; t++)
                    af[i].x[t] = wmma::__float_to_tf32(af[i].x[t]);
            }
            #pragma unroll
            for (int j = 0; j < 4; j++) {
                wmma::load_matrix_sync(bf[j], &Bs[buf][kk][warp_n * 64 + j * 16], LDBS);
                #pragma unroll
                for (int t = 0; t < bf[j].num_elements; t++)
                    bf[j].x[t] = wmma::__float_to_tf32(bf[j].x[t]);
            }
            #pragma unroll
            for (int i = 0; i < 2; i++)
                #pragma unroll
                for (int j = 0; j < 4; j++)
                    wmma::mma_sync(acc[i][j], af[i], bf[j], acc[i][j]);
        }
        __syncthreads();
    }

    #pragma unroll
    for (int i = 0; i < 2; i++) {
        int gr = rowBase + warp_m * 32 + i * 16;
        if (gr >= M) continue;
        #pragma unroll
        for (int j = 0; j < 4; j++) {
            int gc = warp_n * 64 + j * 16;
            wmma::store_matrix_sync(&C[(size_t)gr * OUT2C + gc], acc[i][j], OUT2C, wmma::mem_row_major);
        }
    }
}

// ---------------- 7: layer-2 attention projections --------------------------
__global__ void alpha_proj(const float* __restrict__ h,
                           const float* __restrict__ a_src, const float* __restrict__ a_dst,
                           float* __restrict__ as, float* __restrict__ ad,
                           int n, int heads, int dim)
{
    int gw = (blockIdx.x * blockDim.x + threadIdx.x) >> 5;
    int lane = threadIdx.x & 31;
    if (gw >= n * heads) return;
    int node = gw / heads, hd = gw - node * heads;
    const float* hp = h + (size_t)node * heads * dim + (size_t)hd * dim;
    float s1 = 0.f, s2 = 0.f;
    for (int f = lane; f < dim; f += 32) {
        float v = hp[f];
        s1 += v * a_src[hd * dim + f];
        s2 += v * a_dst[hd * dim + f];
    }
    #pragma unroll
    for (int o = 16; o; o >>= 1) {
        s1 += __shfl_down_sync(0xffffffffu, s1, o);
        s2 += __shfl_down_sync(0xffffffffu, s2, o);
    }
    if (lane == 0) { as[gw] = s1; ad[gw] = s2; }
}

// ---------------- 8: layer-2 gather ----------------
#define CHUNK2 128
__global__ __launch_bounds__(128) void gat_gather2(
    const int* __restrict__ rowptr, const int* __restrict__ csrsrc,
    const float* __restrict__ as, const float* __restrict__ ad,
    const float* __restrict__ h, const float* __restrict__ bias,
    float* __restrict__ out)
{
    int d = blockIdx.x;
    int tid = threadIdx.x;
    int beg = rowptr[d], end = rowptr[d + 1];
    int deg = end - beg;

    __shared__ float ms, dens;
    __shared__ int   s_src[CHUNK2];
    __shared__ float w[CHUNK2];

    float adv = ad[d];
    if (tid == 0) { ms = -INFINITY; dens = 0.f; }
    __syncthreads();

    float acc = 0.f;

    if (deg <= CHUNK2) {
        if (tid < deg) {
            int s = csrsrc[beg + tid];
            s_src[tid] = s;
            float v = as[s] + adv;
            v = v > 0.f ? v : SLOPE * v;
            w[tid] = v;
            atomicMaxF(&ms, v);
        }
        __syncthreads();
        float mv = ms;
        if (tid < deg) {
            float ww = __expf(w[tid] - mv);
            w[tid] = ww;
            atomicAdd(&dens, ww);
        }
        __syncthreads();
        for (int e = 0; e < deg; e++)
            acc += h[(size_t)s_src[e] * OUT2C + tid] * w[e];
    } else {
        for (int t = tid; t < deg; t += 128) {
            float v = as[csrsrc[beg + t]] + adv;
            v = v > 0.f ? v : SLOPE * v;
            atomicMaxF(&ms, v);
        }
        __syncthreads();
        float mv = ms;
        for (int cbeg = 0; cbeg < deg; cbeg += CHUNK2) {
            int clen = min(CHUNK2, deg - cbeg);
            if (tid < clen) {
                int s = csrsrc[beg + cbeg + tid];
                s_src[tid] = s;
                float v = as[s] + adv;
                v = v > 0.f ? v : SLOPE * v;
                float ww = __expf(v - mv);
                w[tid] = ww;
                atomicAdd(&dens, ww);
            }
            __syncthreads();
            for (int e = 0; e < clen; e++)
                acc += h[(size_t)s_src[e] * OUT2C + tid] * w[e];
            __syncthreads();
        }
    }
    __syncthreads();

    float v = acc / (dens + 1e-16f) + bias[tid];
    out[(size_t)d * OUT2C + tid] = v > 0.f ? v : 0.f;
}

// ---------------- 9: gstart ----------------
__global__ void gstart_build(const int* __restrict__ batch, int* __restrict__ gstart) {
    int i = blockIdx.x * blockDim.x + threadIdx.x;
    if (i >= NN) return;
    int b  = batch[i];
    int bp = (i == 0) ? -1 : batch[i - 1];
    for (int g = bp + 1; g <= b; ++g) gstart[g] = i;
    if (i == NN - 1) {
        for (int g = b + 1; g <= GC; ++g) gstart[g] = NN;
    }
}

// ---------------- 10: fused pool(max) + fc + relu ----------------
__global__ __launch_bounds__(128) void pool_fc(
    const float* __restrict__ o2, const int* __restrict__ gstart,
    const float* __restrict__ W, const float* __restrict__ b,
    float* __restrict__ out)
{
    __shared__ float p[OUT2C];
    int g = blockIdx.x, j = threadIdx.x;
    int beg = gstart[g], end = gstart[g + 1];
    float acc = -INFINITY;
    for (int n = beg; n < end; n++)
        acc = fmaxf(acc, o2[(size_t)n * OUT2C + j]);
    p[j] = (beg < end) ? acc : 0.f;
    __syncthreads();
    float s = b[j];
    #pragma unroll 8
    for (int k = 0; k < OUT2C; k++) s += p[k] * W[k * OUT2C + j];
    out[g * OUT2C + j] = s > 0.f ? s : 0.f;
}

// ---------------- 11: cleanup ----------------
__global__ void zero_deg(int* __restrict__ deg) {
    int i = blockIdx.x * blockDim.x + threadIdx.x;
    if (i < NN + 1) deg[i] = 0;
}

// ---------------- launch ----------------
static inline int cdiv(int a, int b) { return (a + b - 1) / b; }

extern "C" void kernel_launch(void* const* d_in, const int* in_sizes, int n_in,
                              void* d_out, int out_size)
{
    const float* x     = (const float*)d_in[0];
    const int*   ei    = (const int*)  d_in[1];
    const int*   batch = (const int*)  d_in[2];
    const float* W1    = (const float*)d_in[4];
    const float* a_s1  = (const float*)d_in[5];
    const float* a_d1  = (const float*)d_in[6];
    const float* b1    = (const float*)d_in[7];
    const float* W2    = (const float*)d_in[8];
    const float* a_s2  = (const float*)d_in[9];
    const float* a_d2  = (const float*)d_in[10];
    const float* b2    = (const float*)d_in[11];
    const float* fcW   = (const float*)d_in[12];
    const float* fcb   = (const float*)d_in[13];
    float* out = (float*)d_out;

    float *agg, *o1, *h2, *o2, *as1, *ad1, *as2, *ad2, *pvec;
    int *deg, *rowptr, *cursor, *csrsrc, *gstart;
    cudaGetSymbolAddress((void**)&agg, g_agg);
    cudaGetSymbolAddress((void**)&o1,  g_o1);
    cudaGetSymbolAddress((void**)&h2,  g_h2);
    cudaGetSymbolAddress((void**)&o2,  g_o2);
    cudaGetSymbolAddress((void**)&as1, g_as1);
    cudaGetSymbolAddress((void**)&ad1, g_ad1);
    cudaGetSymbolAddress((void**)&as2, g_as2);
    cudaGetSymbolAddress((void**)&ad2, g_ad2);
    cudaGetSymbolAddress((void**)&pvec, g_p);
    cudaGetSymbolAddress((void**)&deg,    g_deg);
    cudaGetSymbolAddress((void**)&rowptr, g_rowptr);
    cudaGetSymbolAddress((void**)&cursor, g_cursor);
    cudaGetSymbolAddress((void**)&csrsrc, g_csrsrc);
    cudaGetSymbolAddress((void**)&gstart, g_gstart);

    hist_kernel<<<EDGE_BLOCKS, 256>>>(ei, deg);                              // 1
    scan50k<<<1, 1024>>>(deg, rowptr, cursor, W1, a_s1, a_d1, pvec);         // 2
    csr_scatter_proj<<<EDGE_BLOCKS, 256>>>(ei, cursor, csrsrc, x, pvec, as1, ad1); // 3
    gather1x<<<NN, 256>>>(rowptr, csrsrc, as1, ad1, x, agg);                 // 4 <- ncu
    {
        dim3 grid(cdiv(NN, 128), H1C);
        gemm1h_tf32<<<grid, 256>>>(agg, W1, b1, o1);                         // 5
    }
    gemm2_tf32<<<cdiv(NN, 128), 256>>>(o1, W2, h2, NN);                      // 6
    alpha_proj<<<cdiv(NN * 32, 256), 256>>>(h2, a_s2, a_d2, as2, ad2, NN, 1, OUT2C); // 7
    gat_gather2<<<NN, 128>>>(rowptr, csrsrc, as2, ad2, h2, b2, o2);          // 8
    gstart_build<<<cdiv(NN, 256), 256>>>(batch, gstart);                     // 9
    pool_fc<<<GC, OUT2C>>>(o2, gstart, fcW, fcb, out);                       // 10
    zero_deg<<<cdiv(NN + 1, 256), 256>>>(deg);                               // 11
}

// round 17
// speedup vs baseline: 1.6792x; 1.0029x over previous
#include <cuda_runtime.h>
#include <cuda_bf16.h>
#include <cuda_pipeline.h>
#include <mma.h>
#include <math.h>

using namespace nvcuda;

#define NN    50000
#define EE    800000
#define ETOT  (EE + NN)
#define FIN   78
#define H1C   10
#define D1    (H1C * FIN)   // 780
#define OUT2C 128
#define GC    512
#define SLOPE 0.2f
#define CHUNK 64
#define PROJ_BLOCKS ((NN + 31) / 32)       // 1563
#define EDGE_BLOCKS ((ETOT + 255) / 256)   // 3321

// ---------------- scratch ----------------
__device__ float g_agg[(size_t)NN * D1];
__device__ float g_o1 [(size_t)NN * D1];
__device__ float g_h2 [(size_t)NN * OUT2C];
__device__ float g_o2 [(size_t)NN * OUT2C];
__device__ float g_as1[(size_t)NN * H1C];
__device__ float g_ad1[(size_t)NN * H1C];
__device__ float g_as2[NN];
__device__ float g_ad2[NN];
__device__ float g_p  [20 * FIN];
__device__ int   g_deg[NN + 1];            // zero-init; re-zeroed by pool_fc
__device__ int   g_rowptr[NN + 1];
__device__ int   g_cursor[NN];
__device__ int   g_csrsrc[ETOT];
__device__ int   g_gstart[GC + 1];

// ---------------- helpers ----------------
__device__ __forceinline__ void atomicMaxF(float* addr, float val) {
    if (!signbit(val)) atomicMax((int*)addr, __float_as_int(val));
    else               atomicMin((unsigned int*)addr, __float_as_uint(val));
}
__device__ __forceinline__ void edge_nodes(const int* __restrict__ ei, int t, int& s, int& d) {
    if (t < EE) { s = ei[t]; d = ei[EE + t]; }
    else        { s = t - EE; d = t - EE; }
}

// ---------------- 1: histogram (+ gstart build fused) ----------------
__global__ void hist_gstart(const int* __restrict__ ei, int* __restrict__ deg,
                            const int* __restrict__ batch, int* __restrict__ gstart) {
    int t = blockIdx.x * blockDim.x + threadIdx.x;
    if (t < ETOT) {
        int s, d; edge_nodes(ei, t, s, d);
        atomicAdd(&deg[d], 1);
    }
    if (t < NN) {
        int b  = batch[t];
        int bp = (t == 0) ? -1 : batch[t - 1];
        for (int g = bp + 1; g <= b; ++g) gstart[g] = t;
        if (t == NN - 1)
            for (int g = b + 1; g <= GC; ++g) gstart[g] = NN;
    }
}

// ---------------- 2: scan (shuffle-based) + attention-vector projection -----
__global__ void scan50k(const int* __restrict__ deg, int* __restrict__ rowptr,
                        int* __restrict__ cur,
                        const float* __restrict__ W1, const float* __restrict__ a_src,
                        const float* __restrict__ a_dst, float* __restrict__ p)
{
    for (int idx = threadIdx.x; idx < 20 * FIN; idx += 1024) {
        int o = idx / FIN, k = idx - o * FIN;
        int h = (o < H1C) ? o : o - H1C;
        const float* av = (o < H1C) ? (a_src + h * FIN) : (a_dst + h * FIN);
        const float* wrow = W1 + (size_t)k * D1 + h * FIN;
        float s = 0.f;
        #pragma unroll 13
        for (int f = 0; f < FIN; f++) s += wrow[f] * av[f];
        p[idx] = s;
    }

    __shared__ int warpsum[32];
    __shared__ int carry_s;
    int tid = threadIdx.x, lane = tid & 31, warp = tid >> 5;
    if (tid == 0) carry_s = 0;
    __syncthreads();

    for (int base = 0; base < NN; base += 1024) {
        int i = base + tid;
        int v = (i < NN) ? deg[i] : 0;
        int s = v;
        #pragma unroll
        for (int o = 1; o < 32; o <<= 1) {
            int t = __shfl_up_sync(0xffffffffu, s, o);
            if (lane >= o) s += t;
        }
        if (lane == 31) warpsum[warp] = s;
        __syncthreads();
        if (warp == 0) {
            int ws = warpsum[lane];
            int e = ws;
            #pragma unroll
            for (int o = 1; o < 32; o <<= 1) {
                int t = __shfl_up_sync(0xffffffffu, e, o);
                if (lane >= o) e += t;
            }
            warpsum[lane] = e - ws;
        }
        __syncthreads();
        int excl = carry_s + warpsum[warp] + s - v;
        if (i < NN) { rowptr[i] = excl; cur[i] = excl; }
        __syncthreads();
        if (tid == 1023) carry_s = excl + v;
        __syncthreads();
    }
    if (threadIdx.x == 0) rowptr[NN] = carry_s;
}

// ---------------- 3: CSR scatter + per-node logits as1/ad1 ------------------
__global__ __launch_bounds__(256) void csr_scatter_proj(
    const int* __restrict__ ei, int* __restrict__ cur, int* __restrict__ csrsrc,
    const float* __restrict__ x, const float* __restrict__ p,
    float* __restrict__ as, float* __restrict__ ad)
{
    int b = blockIdx.x, tid = threadIdx.x;
    int t = b * 256 + tid;
    if (t < ETOT) {
        int s, d; edge_nodes(ei, t, s, d);
        int pos = atomicAdd(&cur[d], 1);
        csrsrc[pos] = s;
    }

    if (b < PROJ_BLOCKS) {
        __shared__ float xs[32][80];
        __shared__ float ps[20][80];
        int nodeBase = b * 32;
        for (int idx = tid; idx < 20 * FIN; idx += 256) {
            int o = idx / FIN, k = idx - o * FIN;
            ps[o][k] = p[idx];
        }
        for (int idx = tid; idx < 32 * FIN; idx += 256) {
            int i = idx / FIN, k = idx - i * FIN;
            int n = nodeBase + i;
            xs[i][k] = (n < NN) ? x[(size_t)n * FIN + k] : 0.f;
        }
        __syncthreads();
        for (int s = tid; s < 32 * 20; s += 256) {
            int i = s / 20, o = s - i * 20;
            int n = nodeBase + i;
            if (n >= NN) continue;
            float acc = 0.f;
            #pragma unroll 13
            for (int k = 0; k < FIN; k++) acc += xs[i][k] * ps[o][k];
            if (o < H1C) as[n * H1C + o] = acc;
            else         ad[n * H1C + (o - H1C)] = acc;
        }
    }
}

// ---------------- 4: layer-1 gather (strength-reduced indices) --------------
__global__ __launch_bounds__(256) void gather1x(
    const int* __restrict__ rowptr, const int* __restrict__ csrsrc,
    const float* __restrict__ as, const float* __restrict__ ad,
    const float* __restrict__ x, float* __restrict__ agg)
{
    int d = blockIdx.x;
    int tid = threadIdx.x;
    int beg = rowptr[d], end = rowptr[d + 1];
    int deg = end - beg;

    __shared__ float m[H1C];
    __shared__ float den[H1C];
    __shared__ float adv[H1C];
    __shared__ int   s_src[CHUNK];
    __shared__ float w[CHUNK][H1C];
    __shared__ __align__(16) float xs[CHUNK][80];

    if (tid < H1C) {
        adv[tid] = ad[d * H1C + tid];
        m[tid] = -INFINITY;
        den[tid] = 0.f;
    }
    __syncthreads();

    const bool active = tid < 200;
    int hh = tid / 20;
    int f4 = (tid % 20) * 4;
    float a0 = 0.f, a1 = 0.f, a2 = 0.f, a3 = 0.f;

    // incremental index seeds (computed once)
    const int e40_0 = tid / 40, kp40_0 = tid - e40_0 * 40;   // for stride-256 over *40
    const int e10_0 = tid / 10, h10_0 = tid - e10_0 * 10;    // for stride-256 over *10

    if (deg <= CHUNK) {
        for (int t = tid; t < deg; t += 256) s_src[t] = csrsrc[beg + t];
        __syncthreads();
        // float2 staging with carry counters (256 = 6*40 + 16)
        {
            int e = e40_0, kp = kp40_0;
            for (int t = tid; t < deg * 40; t += 256) {
                if (kp < 39)
                    *(float2*)&xs[e][kp * 2] =
                        *(const float2*)(x + (size_t)s_src[e] * FIN + kp * 2);
                else { xs[e][78] = 0.f; xs[e][79] = 0.f; }
                e += 6; kp += 16;
                if (kp >= 40) { kp -= 40; e += 1; }
            }
        }
        // logits pass 1 (256 = 25*10 + 6)
        {
            int e = e10_0, h = h10_0;
            for (int t = tid; t < deg * H1C; t += 256) {
                float v = as[s_src[e] * H1C + h] + adv[h];
                v = v > 0.f ? v : SLOPE * v;
                w[e][h] = v;
                atomicMaxF(&m[h], v);
                e += 25; h += 6;
                if (h >= 10) { h -= 10; e += 1; }
            }
        }
        __syncthreads();
        {
            int e = e10_0, h = h10_0;
            for (int t = tid; t < deg * H1C; t += 256) {
                float ww = __expf(w[e][h] - m[h]);
                w[e][h] = ww;
                atomicAdd(&den[h], ww);
                e += 25; h += 6;
                if (h >= 10) { h -= 10; e += 1; }
            }
        }
        __syncthreads();
        if (active) {
            for (int e = 0; e < deg; e++) {
                float4 xv = *(const float4*)&xs[e][f4];
                float ww = w[e][hh];
                a0 += xv.x * ww; a1 += xv.y * ww; a2 += xv.z * ww; a3 += xv.w * ww;
            }
        }
    } else {
        // max pass over all edges
        {
            int e = e10_0, h = h10_0;
            for (int t = tid; t < deg * H1C; t += 256) {
                int s = csrsrc[beg + e];
                float v = as[s * H1C + h] + adv[h];
                v = v > 0.f ? v : SLOPE * v;
                atomicMaxF(&m[h], v);
                e += 25; h += 6;
                if (h >= 10) { h -= 10; e += 1; }
            }
        }
        __syncthreads();
        for (int cbeg = 0; cbeg < deg; cbeg += CHUNK) {
            int clen = min(CHUNK, deg - cbeg);
            for (int t = tid; t < clen; t += 256) s_src[t] = csrsrc[beg + cbeg + t];
            __syncthreads();
            {
                int e = e40_0, kp = kp40_0;
                for (int t = tid; t < clen * 40; t += 256) {
                    if (kp < 39)
                        *(float2*)&xs[e][kp * 2] =
                            *(const float2*)(x + (size_t)s_src[e] * FIN + kp * 2);
                    else { xs[e][78] = 0.f; xs[e][79] = 0.f; }
                    e += 6; kp += 16;
                    if (kp >= 40) { kp -= 40; e += 1; }
                }
            }
            {
                int e = e10_0, h = h10_0;
                for (int t = tid; t < clen * H1C; t += 256) {
                    float v = as[s_src[e] * H1C + h] + adv[h];
                    v = v > 0.f ? v : SLOPE * v;
                    float ww = __expf(v - m[h]);
                    w[e][h] = ww;
                    atomicAdd(&den[h], ww);
                    e += 25; h += 6;
                    if (h >= 10) { h -= 10; e += 1; }
                }
            }
            __syncthreads();
            if (active) {
                for (int e = 0; e < clen; e++) {
                    float4 xv = *(const float4*)&xs[e][f4];
                    float ww = w[e][hh];
                    a0 += xv.x * ww; a1 += xv.y * ww; a2 += xv.z * ww; a3 += xv.w * ww;
                }
            }
            __syncthreads();
        }
    }
    __syncthreads();

    if (active) {
        float inv = 1.f / (den[hh] + 1e-16f);
        float* op = agg + (size_t)d * D1 + hh * FIN + f4;
        op[0] = a0 * inv;
        if (f4 + 1 < FIN) op[1] = a1 * inv;
        if (f4 + 2 < FIN) op[2] = a2 * inv;
        if (f4 + 3 < FIN) op[3] = a3 * inv;
    }
}

// ---------------- 5: per-head TF32 GEMM + bias + relu -----------------------
#define LDA1 20
#define LDB1 88
#define LDC1 84
__global__ __launch_bounds__(256) void gemm1h_tf32(
    const float* __restrict__ agg, const float* __restrict__ W1,
    const float* __restrict__ b1, float* __restrict__ o1)
{
    __shared__ __align__(16) float As[128][LDA1];
    __shared__ __align__(16) float Bs[16][LDB1];
    __shared__ __align__(16) float Cs[64][LDC1];

    int h = blockIdx.y;
    int rowBase = blockIdx.x * 128;
    int tid = threadIdx.x;
    int warp = tid >> 5;
    const float* Abase = agg + h * FIN;
    const float* Bbase = W1 + h * FIN;

    wmma::fragment<wmma::accumulator, 16, 16, 8, float> acc[5];
    #pragma unroll
    for (int j = 0; j < 5; j++) wmma::fill_fragment(acc[j], 0.f);

    for (int k0 = 0; k0 < FIN; k0 += 16) {
        #pragma unroll
        for (int l = 0; l < 4; l++) {
            int idx = tid + l * 256;
            int r = idx >> 3, pr = idx & 7;
            int gk = k0 + pr * 2;
            int gr = rowBase + r;
            float2 v = make_float2(0.f, 0.f);
            if (gr < NN && gk < FIN)
                v = *(const float2*)(Abase + (size_t)gr * D1 + gk);
            *(float2*)&As[r][pr * 2] = v;
        }
        for (int idx = tid; idx < 640; idx += 256) {
            int r = idx / 40, pc = idx % 40;
            int gk = k0 + r, gc = pc * 2;
            float2 v = make_float2(0.f, 0.f);
            if (gk < FIN && gc < FIN)
                v = *(const float2*)(Bbase + (size_t)gk * D1 + gc);
            *(float2*)&Bs[r][pc * 2] = v;
        }
        __syncthreads();

        #pragma unroll
        for (int kk = 0; kk < 16; kk += 8) {
            wmma::fragment<wmma::matrix_a, 16, 16, 8, wmma::precision::tf32, wmma::row_major> af;
            wmma::load_matrix_sync(af, &As[warp * 16][kk], LDA1);
            #pragma unroll
            for (int t = 0; t < af.num_elements; t++) af.x[t] = wmma::__float_to_tf32(af.x[t]);
            #pragma unroll
            for (int j = 0; j < 5; j++) {
                wmma::fragment<wmma::matrix_b, 16, 16, 8, wmma::precision::tf32, wmma::row_major> bf;
                wmma::load_matrix_sync(bf, &Bs[kk][j * 16], LDB1);
                #pragma unroll
                for (int t = 0; t < bf.num_elements; t++) bf.x[t] = wmma::__float_to_tf32(bf.x[t]);
                wmma::mma_sync(acc[j], af, bf, acc[j]);
            }
        }
        __syncthreads();
    }

    for (int p = 0; p < 2; p++) {
        if (warp >= p * 4 && warp < p * 4 + 4) {
            int lr = (warp - p * 4) * 16;
            #pragma unroll
            for (int j = 0; j < 5; j++)
                wmma::store_matrix_sync(&Cs[lr][j * 16], acc[j], LDC1, wmma::mem_row_major);
        }
        __syncthreads();
        for (int idx = tid; idx < 64 * FIN; idx += 256) {
            int r = idx / FIN, c = idx - r * FIN;
            int gr = rowBase + p * 64 + r;
            if (gr < NN) {
                float v = Cs[r][c] + b1[h * FIN + c];
                o1[(size_t)gr * D1 + h * FIN + c] = v > 0.f ? v : 0.f;
            }
        }
        __syncthreads();
    }
}

// ---------------- 6: layer-2 GEMM, TF32 tensor cores, cp.async pipeline -----
#define K2    780
#define NCH   49
#define LDAS  20
#define LDBS  136

__global__ __launch_bounds__(256) void gemm2_tf32(
    const float* __restrict__ A, const float* __restrict__ B, float* __restrict__ C, int M)
{
    __shared__ float As[2][128][LDAS];
    __shared__ float Bs[2][16][LDBS];

    int tid = threadIdx.x;
    int warp = tid >> 5;
    int warp_m = warp & 3;
    int warp_n = warp >> 2;
    int rowBase = blockIdx.x * 128;

    wmma::fragment<wmma::accumulator, 16, 16, 8, float> acc[2][4];
    #pragma unroll
    for (int i = 0; i < 2; i++)
        #pragma unroll
        for (int j = 0; j < 4; j++) wmma::fill_fragment(acc[i][j], 0.f);

    auto load_stage = [&](int ch, int buf) {
        int k0 = ch * 16;
        #pragma unroll
        for (int l = 0; l < 2; l++) {
            int idx = tid + l * 256;
            int r = idx >> 2, c4 = idx & 3;
            int gr = rowBase + r;
            int gk = k0 + c4 * 4;
            bool valid = (gr < M) && (gk < K2);
            const float* src = A + (size_t)gr * K2 + gk;
            __pipeline_memcpy_async(&As[buf][r][c4 * 4], src, 16, valid ? 0 : 16);
        }
        #pragma unroll
        for (int l = 0; l < 2; l++) {
            int idx = tid + l * 256;
            int r = idx >> 5, c = idx & 31;
            int gk = k0 + r;
            bool valid = (gk < K2);
            const float* src = B + (size_t)gk * OUT2C + c * 4;
            __pipeline_memcpy_async(&Bs[buf][r][c * 4], src, 16, valid ? 0 : 16);
        }
        __pipeline_commit();
    };

    load_stage(0, 0);

    for (int ch = 0; ch < NCH; ch++) {
        int buf = ch & 1;
        if (ch + 1 < NCH) load_stage(ch + 1, (ch + 1) & 1);
        __pipeline_wait_prior((ch + 1 < NCH) ? 1 : 0);
        __syncthreads();

        #pragma unroll
        for (int kk = 0; kk < 16; kk += 8) {
            wmma::fragment<wmma::matrix_a, 16, 16, 8, wmma::precision::tf32, wmma::row_major> af[2];
            wmma::fragment<wmma::matrix_b, 16, 16, 8, wmma::precision::tf32, wmma::row_major> bf[4];
            #pragma unroll
            for (int i = 0; i < 2; i++) {
                wmma::load_matrix_sync(af[i], &As[buf][warp_m * 32 + i * 16][kk], LDAS);
                #pragma unroll
                for (int t = 0; t < af[i].num_elements; t++)
                    af[i].x[t] = wmma::__float_to_tf32(af[i].x[t]);
            }
            #pragma unroll
            for (int j = 0; j < 4; j++) {
                wmma::load_matrix_sync(bf[j], &Bs[buf][kk][warp_n * 64 + j * 16], LDBS);
                #pragma unroll
                for (int t = 0; t < bf[j].num_elements; t++)
                    bf[j].x[t] = wmma::__float_to_tf32(bf[j].x[t]);
            }
            #pragma unroll
            for (int i = 0; i < 2; i++)
                #pragma unroll
                for (int j = 0; j < 4; j++)
                    wmma::mma_sync(acc[i][j], af[i], bf[j], acc[i][j]);
        }
        __syncthreads();
    }

    #pragma unroll
    for (int i = 0; i < 2; i++) {
        int gr = rowBase + warp_m * 32 + i * 16;
        if (gr >= M) continue;
        #pragma unroll
        for (int j = 0; j < 4; j++) {
            int gc = warp_n * 64 + j * 16;
            wmma::store_matrix_sync(&C[(size_t)gr * OUT2C + gc], acc[i][j], OUT2C, wmma::mem_row_major);
        }
    }
}

// ---------------- 7: layer-2 attention projections --------------------------
__global__ void alpha_proj(const float* __restrict__ h,
                           const float* __restrict__ a_src, const float* __restrict__ a_dst,
                           float* __restrict__ as, float* __restrict__ ad,
                           int n, int heads, int dim)
{
    int gw = (blockIdx.x * blockDim.x + threadIdx.x) >> 5;
    int lane = threadIdx.x & 31;
    if (gw >= n * heads) return;
    int node = gw / heads, hd = gw - node * heads;
    const float* hp = h + (size_t)node * heads * dim + (size_t)hd * dim;
    float s1 = 0.f, s2 = 0.f;
    for (int f = lane; f < dim; f += 32) {
        float v = hp[f];
        s1 += v * a_src[hd * dim + f];
        s2 += v * a_dst[hd * dim + f];
    }
    #pragma unroll
    for (int o = 16; o; o >>= 1) {
        s1 += __shfl_down_sync(0xffffffffu, s1, o);
        s2 += __shfl_down_sync(0xffffffffu, s2, o);
    }
    if (lane == 0) { as[gw] = s1; ad[gw] = s2; }
}

// ---------------- 8: layer-2 gather (split-half float2) ---------------------
#define CHUNK2 128
__global__ __launch_bounds__(128) void gat_gather2(
    const int* __restrict__ rowptr, const int* __restrict__ csrsrc,
    const float* __restrict__ as, const float* __restrict__ ad,
    const float* __restrict__ h, const float* __restrict__ bias,
    float* __restrict__ out)
{
    int d = blockIdx.x;
    int tid = threadIdx.x;
    int half = tid >> 6, l64 = tid & 63;
    int beg = rowptr[d], end = rowptr[d + 1];
    int deg = end - beg;

    __shared__ float ms, dens;
    __shared__ int   s_src[CHUNK2];
    __shared__ float w[CHUNK2];
    __shared__ float accs[OUT2C];

    float adv = ad[d];
    if (tid == 0) { ms = -INFINITY; dens = 0.f; }
    __syncthreads();

    float2 acc = make_float2(0.f, 0.f);

    if (deg <= CHUNK2) {
        if (tid < deg) {
            int s = csrsrc[beg + tid];
            s_src[tid] = s;
            float v = as[s] + adv;
            v = v > 0.f ? v : SLOPE * v;
            w[tid] = v;
            atomicMaxF(&ms, v);
        }
        __syncthreads();
        float mv = ms;
        if (tid < deg) {
            float ww = __expf(w[tid] - mv);
            w[tid] = ww;
            atomicAdd(&dens, ww);
        }
        __syncthreads();
        for (int e = half; e < deg; e += 2) {
            float2 hv = *(const float2*)(h + (size_t)s_src[e] * OUT2C + l64 * 2);
            float ww = w[e];
            acc.x += hv.x * ww; acc.y += hv.y * ww;
        }
    } else {
        for (int t = tid; t < deg; t += 128) {
            float v = as[csrsrc[beg + t]] + adv;
            v = v > 0.f ? v : SLOPE * v;
            atomicMaxF(&ms, v);
        }
        __syncthreads();
        float mv = ms;
        for (int cbeg = 0; cbeg < deg; cbeg += CHUNK2) {
            int clen = min(CHUNK2, deg - cbeg);
            if (tid < clen) {
                int s = csrsrc[beg + cbeg + tid];
                s_src[tid] = s;
                float v = as[s] + adv;
                v = v > 0.f ? v : SLOPE * v;
                float ww = __expf(v - mv);
                w[tid] = ww;
                atomicAdd(&dens, ww);
            }
            __syncthreads();
            for (int e = half; e < clen; e += 2) {
                float2 hv = *(const float2*)(h + (size_t)s_src[e] * OUT2C + l64 * 2);
                float ww = w[e];
                acc.x += hv.x * ww; acc.y += hv.y * ww;
            }
            __syncthreads();
        }
    }
    __syncthreads();

    // combine halves
    if (half == 1) { accs[l64 * 2] = acc.x; accs[l64 * 2 + 1] = acc.y; }
    __syncthreads();
    if (half == 0) {
        float inv = 1.f / (dens + 1e-16f);
        float v0 = (acc.x + accs[l64 * 2])     * inv + bias[l64 * 2];
        float v1 = (acc.y + accs[l64 * 2 + 1]) * inv + bias[l64 * 2 + 1];
        float2 o = make_float2(v0 > 0.f ? v0 : 0.f, v1 > 0.f ? v1 : 0.f);
        *(float2*)(out + (size_t)d * OUT2C + l64 * 2) = o;
    }
}

// ---------------- 9: fused pool(max) + fc + relu (+ deg cleanup) ------------
__global__ __launch_bounds__(128) void pool_fc(
    const float* __restrict__ o2, const int* __restrict__ gstart,
    const float* __restrict__ W, const float* __restrict__ b,
    float* __restrict__ out, int* __restrict__ deg)
{
    // cleanup for next replay (512*128 = 65536 >= NN+1)
    int cid = blockIdx.x * 128 + threadIdx.x;
    if (cid < NN + 1) deg[cid] = 0;

    __shared__ float p[OUT2C];
    int g = blockIdx.x, j = threadIdx.x;
    int beg = gstart[g], end = gstart[g + 1];
    float acc = -INFINITY;
    for (int n = beg; n < end; n++)
        acc = fmaxf(acc, o2[(size_t)n * OUT2C + j]);
    p[j] = (beg < end) ? acc : 0.f;
    __syncthreads();
    float s = b[j];
    #pragma unroll 8
    for (int k = 0; k < OUT2C; k++) s += p[k] * W[k * OUT2C + j];
    out[g * OUT2C + j] = s > 0.f ? s : 0.f;
}

// ---------------- launch ----------------
static inline int cdiv(int a, int b) { return (a + b - 1) / b; }

extern "C" void kernel_launch(void* const* d_in, const int* in_sizes, int n_in,
                              void* d_out, int out_size)
{
    const float* x     = (const float*)d_in[0];
    const int*   ei    = (const int*)  d_in[1];
    const int*   batch = (const int*)  d_in[2];
    const float* W1    = (const float*)d_in[4];
    const float* a_s1  = (const float*)d_in[5];
    const float* a_d1  = (const float*)d_in[6];
    const float* b1    = (const float*)d_in[7];
    const float* W2    = (const float*)d_in[8];
    const float* a_s2  = (const float*)d_in[9];
    const float* a_d2  = (const float*)d_in[10];
    const float* b2    = (const float*)d_in[11];
    const float* fcW   = (const float*)d_in[12];
    const float* fcb   = (const float*)d_in[13];
    float* out = (float*)d_out;

    float *agg, *o1, *h2, *o2, *as1, *ad1, *as2, *ad2, *pvec;
    int *deg, *rowptr, *cursor, *csrsrc, *gstart;
    cudaGetSymbolAddress((void**)&agg, g_agg);
    cudaGetSymbolAddress((void**)&o1,  g_o1);
    cudaGetSymbolAddress((void**)&h2,  g_h2);
    cudaGetSymbolAddress((void**)&o2,  g_o2);
    cudaGetSymbolAddress((void**)&as1, g_as1);
    cudaGetSymbolAddress((void**)&ad1, g_ad1);
    cudaGetSymbolAddress((void**)&as2, g_as2);
    cudaGetSymbolAddress((void**)&ad2, g_ad2);
    cudaGetSymbolAddress((void**)&pvec, g_p);
    cudaGetSymbolAddress((void**)&deg,    g_deg);
    cudaGetSymbolAddress((void**)&rowptr, g_rowptr);
    cudaGetSymbolAddress((void**)&cursor, g_cursor);
    cudaGetSymbolAddress((void**)&csrsrc, g_csrsrc);
    cudaGetSymbolAddress((void**)&gstart, g_gstart);

    hist_gstart<<<EDGE_BLOCKS, 256>>>(ei, deg, batch, gstart);               // 1
    scan50k<<<1, 1024>>>(deg, rowptr, cursor, W1, a_s1, a_d1, pvec);         // 2
    csr_scatter_proj<<<EDGE_BLOCKS, 256>>>(ei, cursor, csrsrc, x, pvec, as1, ad1); // 3
    gather1x<<<NN, 256>>>(rowptr, csrsrc, as1, ad1, x, agg);                 // 4 <- ncu
    {
        dim3 grid(cdiv(NN, 128), H1C);
        gemm1h_tf32<<<grid, 256>>>(agg, W1, b1, o1);                         // 5
    }
    gemm2_tf32<<<cdiv(NN, 128), 256>>>(o1, W2, h2, NN);                      // 6
    alpha_proj<<<cdiv(NN * 32, 256), 256>>>(h2, a_s2, a_d2, as2, ad2, NN, 1, OUT2C); // 7
    gat_gather2<<<NN, 128>>>(rowptr, csrsrc, as2, ad2, h2, b2, o2);          // 8
    pool_fc<<<GC, OUT2C>>>(o2, gstart, fcW, fcb, out, deg);                  // 9
}